// round 2
// baseline (speedup 1.0000x reference)
#include <cuda_runtime.h>

#define NN 100000
#define EE 1600000
#define HH 64
#define THV 0.7f
#define ATTV 0.2f
#define EPSV 1e-5f
#define SBLK 98
#define WPN_BLOCKS 12500   // warp-per-node: NN/8 warps-of-block(8 warps)

__device__ float g_buf[6][NN*HH];
__device__ float g_V[NN*HH];
__device__ unsigned long long g_bits[NN];
__device__ int g_cnt1[NN], g_cnt2[NN];
__device__ int g_rowptr[NN+1], g_cursor[NN];
__device__ int g_col[EE];
__device__ float g_c1[EE], g_c2[EE];
__device__ float g_dis1[NN], g_dis2[NN];
__device__ double g_stats[18][2][HH];
__device__ float g_wsum[HH];
__device__ int g_bsum[SBLK], g_boff[SBLK];

// ---------------- setup ----------------
__global__ void k_zero() {
    int i = blockIdx.x * blockDim.x + threadIdx.x;
    if (i < NN*HH) g_V[i] = 0.f;
    if (i < NN) { g_cnt1[i] = 0; g_cnt2[i] = 0; }
    if (i < 18*2*HH) ((double*)g_stats)[i] = 0.0;
}

__global__ void k_count(const int* __restrict__ ei, const int* __restrict__ mk) {
    int e = blockIdx.x * blockDim.x + threadIdx.x;
    if (e >= EE) return;
    int dst = ei[EE + e];
    atomicAdd(&g_cnt1[dst], 1);
    if (mk[e]) atomicAdd(&g_cnt2[dst], 1);
}

__global__ void k_scanA() {
    int t = threadIdx.x, b = blockIdx.x;
    int i = b * 1024 + t;
    int v = (i < NN) ? g_cnt1[i] : 0;
    int x = v;
    #pragma unroll
    for (int o = 1; o < 32; o <<= 1) {
        int y = __shfl_up_sync(0xffffffffu, x, o);
        if ((t & 31) >= o) x += y;
    }
    __shared__ int sw[32];
    if ((t & 31) == 31) sw[t >> 5] = x;
    __syncthreads();
    if (t < 32) {
        int y = sw[t], z = y;
        #pragma unroll
        for (int o = 1; o < 32; o <<= 1) {
            int w = __shfl_up_sync(0xffffffffu, z, o);
            if (t >= o) z += w;
        }
        sw[t] = z - y;
    }
    __syncthreads();
    int incl = x + sw[t >> 5];
    if (i < NN) g_rowptr[i] = incl - v;
    if (t == 1023) g_bsum[b] = incl;
}

__global__ void k_scanB() {
    if (threadIdx.x == 0) {
        int run = 0;
        for (int b = 0; b < SBLK; b++) { g_boff[b] = run; run += g_bsum[b]; }
        g_rowptr[NN] = run;
    }
}

__global__ void k_scanC() {
    int i = blockIdx.x * blockDim.x + threadIdx.x;
    if (i >= NN) return;
    int r = g_rowptr[i] + g_boff[i >> 10];
    g_rowptr[i] = r;
    g_cursor[i] = r;
    g_dis1[i] = rsqrtf(1.0f + (float)g_cnt1[i]);
    g_dis2[i] = rsqrtf(1.0f + (float)g_cnt2[i]);
}

__global__ void k_scatter(const int* __restrict__ ei, const int* __restrict__ mk) {
    int e = blockIdx.x * blockDim.x + threadIdx.x;
    if (e >= EE) return;
    int src = ei[e], dst = ei[EE + e];
    int m = mk[e];
    int p = atomicAdd(&g_cursor[dst], 1);
    g_col[p] = src;
    g_c1[p] = g_dis1[src] * g_dis1[dst];
    g_c2[p] = m ? (g_dis2[src] * g_dis2[dst]) : 0.f;
}

__global__ void k_wsum(const float* __restrict__ Wl) {
    int t = threadIdx.x;
    if (t < HH) {
        float s = 0.f;
        for (int j = 0; j < HH; j++) s += Wl[t*HH + j];
        g_wsum[t] = s;
    }
}

// ---------------- aggregations ----------------
__global__ void k_agg_dual(const float* __restrict__ x) {
    int gw = (blockIdx.x * blockDim.x + threadIdx.x) >> 5;
    int lane = threadIdx.x & 31;
    if (gw >= NN) return;
    int n = gw, f0 = lane, f1 = lane + 32;
    float d1 = g_dis1[n], d2 = g_dis2[n];
    float x0 = x[n*HH + f0], x1 = x[n*HH + f1];
    float a10 = d1*d1*x0, a11 = d1*d1*x1;
    float a20 = d2*d2*x0, a21 = d2*d2*x1;
    int s = g_rowptr[n], e = g_rowptr[n+1];
    for (int base = s; base < e; base += 32) {
        int idx = base + lane;
        int cm = 0; float c1 = 0.f, c2 = 0.f;
        if (idx < e) { cm = g_col[idx]; c1 = g_c1[idx]; c2 = g_c2[idx]; }
        int cnt = min(32, e - base);
        for (int j = 0; j < cnt; j += 4) {
            float xa0[4], xa1[4], cc1[4], cc2[4];
            #pragma unroll
            for (int i = 0; i < 4; i++) {
                int jj = j + i;
                int sm = __shfl_sync(0xffffffffu, cm, jj & 31);
                float t1 = __shfl_sync(0xffffffffu, c1, jj & 31);
                float t2 = __shfl_sync(0xffffffffu, c2, jj & 31);
                bool ok = jj < cnt;
                cc1[i] = ok ? t1 : 0.f;
                cc2[i] = ok ? t2 : 0.f;
                int sn = ok ? sm : 0;
                xa0[i] = x[sn*HH + f0];
                xa1[i] = x[sn*HH + f1];
            }
            #pragma unroll
            for (int i = 0; i < 4; i++) {
                a10 = fmaf(cc1[i], xa0[i], a10); a11 = fmaf(cc1[i], xa1[i], a11);
                a20 = fmaf(cc2[i], xa0[i], a20); a21 = fmaf(cc2[i], xa1[i], a21);
            }
        }
    }
    g_buf[0][n*HH+f0] = a10; g_buf[0][n*HH+f1] = a11;
    g_buf[1][n*HH+f0] = a20; g_buf[1][n*HH+f1] = a21;
}

__global__ void k_aggbits(int pass, int outIdx) {
    int gw = (blockIdx.x * blockDim.x + threadIdx.x) >> 5;
    int lane = threadIdx.x & 31;
    if (gw >= NN) return;
    int n = gw;
    const float* coef = pass ? g_c2 : g_c1;
    float d = pass ? g_dis2[n] : g_dis1[n];
    unsigned long long sb = g_bits[n];
    float self = d*d;
    float a0 = self * (float)((unsigned)(sb)       >> lane & 1u);
    float a1 = self * (float)((unsigned)(sb >> 32) >> lane & 1u);
    int s = g_rowptr[n], e = g_rowptr[n+1];
    for (int base = s; base < e; base += 32) {
        int idx = base + lane;
        int cm = 0; float c = 0.f;
        if (idx < e) { cm = g_col[idx]; c = coef[idx]; }
        int cnt = min(32, e - base);
        for (int j = 0; j < cnt; j += 4) {
            unsigned blo[4], bhi[4]; float cc[4];
            #pragma unroll
            for (int i = 0; i < 4; i++) {
                int jj = j + i;
                int sm = __shfl_sync(0xffffffffu, cm, jj & 31);
                float t = __shfl_sync(0xffffffffu, c, jj & 31);
                bool ok = jj < cnt;
                cc[i] = ok ? t : 0.f;
                unsigned long long b = g_bits[ok ? sm : 0];
                blo[i] = (unsigned)b; bhi[i] = (unsigned)(b >> 32);
            }
            #pragma unroll
            for (int i = 0; i < 4; i++) {
                a0 = fmaf(cc[i], (float)((blo[i] >> lane) & 1u), a0);
                a1 = fmaf(cc[i], (float)((bhi[i] >> lane) & 1u), a1);
            }
        }
    }
    g_buf[outIdx][n*HH+lane]    = a0;
    g_buf[outIdx][n*HH+lane+32] = a1;
}

// ---------------- GEMM: Y = A@W + b, fused BN-stat accumulation ----------------
__global__ void __launch_bounds__(128) k_gemm(int aIdx, const float* __restrict__ W,
                                              const float* __restrict__ bias,
                                              int yIdx, int st) {
    const float* A = g_buf[aIdx];
    float* Y = g_buf[yIdx];
    __shared__ float As[64*128];
    __shared__ float Ws[64*64];
    int tid = threadIdx.x;
    int base = blockIdx.x * 128;

    const float4* W4 = (const float4*)W;
    float4* Ws4 = (float4*)Ws;
    #pragma unroll
    for (int i = 0; i < 8; i++) Ws4[tid + 128*i] = W4[tid + 128*i];

    int row = base + tid;
    if (row < NN) {
        const float4* Ar = (const float4*)(A + row*HH);
        #pragma unroll
        for (int v = 0; v < 16; v++) {
            float4 q = Ar[v];
            As[(4*v+0)*128 + tid] = q.x; As[(4*v+1)*128 + tid] = q.y;
            As[(4*v+2)*128 + tid] = q.z; As[(4*v+3)*128 + tid] = q.w;
        }
    } else {
        #pragma unroll
        for (int v = 0; v < 64; v++) As[v*128 + tid] = 0.f;
    }
    __syncthreads();

    int cx = tid & 7, ry = tid >> 3;
    float acc[8][8];
    #pragma unroll
    for (int r = 0; r < 8; r++)
        #pragma unroll
        for (int c = 0; c < 8; c++) acc[r][c] = 0.f;

    #pragma unroll 4
    for (int k = 0; k < 64; k++) {
        float4 a0 = *(const float4*)&As[k*128 + 8*ry];
        float4 a1 = *(const float4*)&As[k*128 + 8*ry + 4];
        float4 w0 = *(const float4*)&Ws[k*64 + 8*cx];
        float4 w1 = *(const float4*)&Ws[k*64 + 8*cx + 4];
        float a[8] = {a0.x,a0.y,a0.z,a0.w,a1.x,a1.y,a1.z,a1.w};
        float w[8] = {w0.x,w0.y,w0.z,w0.w,w1.x,w1.y,w1.z,w1.w};
        #pragma unroll
        for (int r = 0; r < 8; r++)
            #pragma unroll
            for (int c = 0; c < 8; c++)
                acc[r][c] = fmaf(a[r], w[c], acc[r][c]);
    }

    __syncthreads();
    float* ssum = Ws;        // reuse smem
    float* ssq  = Ws + 64;
    if (tid < 64) { ssum[tid] = 0.f; ssq[tid] = 0.f; }
    __syncthreads();

    float b8[8];
    #pragma unroll
    for (int c = 0; c < 8; c++) b8[c] = bias[8*cx + c];
    float ls[8], lq[8];
    #pragma unroll
    for (int c = 0; c < 8; c++) { ls[c] = 0.f; lq[c] = 0.f; }

    #pragma unroll
    for (int r = 0; r < 8; r++) {
        int grow = base + 8*ry + r;
        if (grow < NN) {
            float vals[8];
            #pragma unroll
            for (int c = 0; c < 8; c++) {
                float v = acc[r][c] + b8[c];
                vals[c] = v; ls[c] += v; lq[c] = fmaf(v, v, lq[c]);
            }
            *(float4*)&Y[grow*HH + 8*cx]     = make_float4(vals[0],vals[1],vals[2],vals[3]);
            *(float4*)&Y[grow*HH + 8*cx + 4] = make_float4(vals[4],vals[5],vals[6],vals[7]);
        }
    }
    #pragma unroll
    for (int c = 0; c < 8; c++) {
        atomicAdd(&ssum[8*cx + c], ls[c]);
        atomicAdd(&ssq[8*cx + c],  lq[c]);
    }
    __syncthreads();
    if (tid < 64) {
        atomicAdd(&g_stats[st][0][tid], (double)ssum[tid]);
        atomicAdd(&g_stats[st][1][tid], (double)ssq[tid]);
    }
}

// ---------------- BN helper ----------------
__device__ __forceinline__ float2 bn_coef(int st, int f, const float* __restrict__ g,
                                          const float* __restrict__ b) {
    double s = g_stats[st][0][f], q = g_stats[st][1][f];
    double mean = s * (1.0 / NN);
    float var = (float)(q * (1.0 / NN) - mean * mean);
    float rstd = rsqrtf(var + EPSV);
    float sc = g[f] * rstd;
    float sh = b[f] - (float)mean * sc;
    return make_float2(sc, sh);
}

// bn(Y), optionally store result, stateful conv_lif -> g_bits + V update
__global__ void k_lif(int yIdx, int st, const float* __restrict__ g,
                      const float* __restrict__ b, int storeIdx) {
    int gw = (blockIdx.x * blockDim.x + threadIdx.x) >> 5;
    int lane = threadIdx.x & 31;
    if (gw >= NN) return;
    int n = gw, f0 = lane, f1 = lane + 32;
    float2 c0 = bn_coef(st, f0, g, b);
    float2 c1 = bn_coef(st, f1, g, b);
    const float* Y = g_buf[yIdx];
    float x0 = fmaf(Y[n*HH+f0], c0.x, c0.y);
    float x1 = fmaf(Y[n*HH+f1], c1.x, c1.y);
    if (storeIdx >= 0) { g_buf[storeIdx][n*HH+f0] = x0; g_buf[storeIdx][n*HH+f1] = x1; }
    float v0 = g_V[n*HH+f0] + x0;
    float v1 = g_V[n*HH+f1] + x1;
    bool s0 = v0 >= THV, s1 = v1 >= THV;
    g_V[n*HH+f0] = s0 ? 0.f : v0;
    g_V[n*HH+f1] = s1 ? 0.f : v1;
    unsigned lo = __ballot_sync(0xffffffffu, s0);
    unsigned hi = __ballot_sync(0xffffffffu, s1);
    if (lane == 0) g_bits[n] = (unsigned long long)lo | ((unsigned long long)hi << 32);
}

// bn(Y) -> store, zero-state spike -> g_bits
__global__ void k_bnspike(int yIdx, int st, const float* __restrict__ g,
                          const float* __restrict__ b, int storeIdx) {
    int gw = (blockIdx.x * blockDim.x + threadIdx.x) >> 5;
    int lane = threadIdx.x & 31;
    if (gw >= NN) return;
    int n = gw, f0 = lane, f1 = lane + 32;
    float2 c0 = bn_coef(st, f0, g, b);
    float2 c1 = bn_coef(st, f1, g, b);
    const float* Y = g_buf[yIdx];
    float x0 = fmaf(Y[n*HH+f0], c0.x, c0.y);
    float x1 = fmaf(Y[n*HH+f1], c1.x, c1.y);
    g_buf[storeIdx][n*HH+f0] = x0;
    g_buf[storeIdx][n*HH+f1] = x1;
    unsigned lo = __ballot_sync(0xffffffffu, x0 >= THV);
    unsigned hi = __ballot_sync(0xffffffffu, x1 >= THV);
    if (lane == 0) g_bits[n] = (unsigned long long)lo | ((unsigned long long)hi << 32);
}

// out = add + scale*bn(Y, st); accumulate stats of out into stOut
__global__ void k_addstats(int yIdx, int st, const float* __restrict__ g,
                           const float* __restrict__ b, int addIdx, float scale,
                           int outIdx, int stOut) {
    int lane = threadIdx.x & 31;
    int wid = (blockIdx.x * blockDim.x + threadIdx.x) >> 5;
    int nw = (gridDim.x * blockDim.x) >> 5;
    int f0 = lane, f1 = lane + 32;
    float2 c0 = bn_coef(st, f0, g, b);
    float2 c1 = bn_coef(st, f1, g, b);
    const float* Y = g_buf[yIdx];
    const float* Ad = g_buf[addIdx];
    float* O = g_buf[outIdx];
    float ls0 = 0.f, lq0 = 0.f, ls1 = 0.f, lq1 = 0.f;
    for (int n = wid; n < NN; n += nw) {
        float t0 = fmaf(scale, fmaf(Y[n*HH+f0], c0.x, c0.y), Ad[n*HH+f0]);
        float t1 = fmaf(scale, fmaf(Y[n*HH+f1], c1.x, c1.y), Ad[n*HH+f1]);
        O[n*HH+f0] = t0; O[n*HH+f1] = t1;
        ls0 += t0; lq0 = fmaf(t0, t0, lq0);
        ls1 += t1; lq1 = fmaf(t1, t1, lq1);
    }
    __shared__ float ss[64], sq[64];
    if (threadIdx.x < 64) { ss[threadIdx.x] = 0.f; sq[threadIdx.x] = 0.f; }
    __syncthreads();
    atomicAdd(&ss[f0], ls0); atomicAdd(&sq[f0], lq0);
    atomicAdd(&ss[f1], ls1); atomicAdd(&sq[f1], lq1);
    __syncthreads();
    if (threadIdx.x < 64) {
        atomicAdd(&g_stats[stOut][0][threadIdx.x], (double)ss[threadIdx.x]);
        atomicAdd(&g_stats[stOut][1][threadIdx.x], (double)sq[threadIdx.x]);
    }
}

// q/k/v spikes, qk attention spike, att bits -> g_bits
__global__ void k_qkv(int qIdx, int kIdx, int vIdx, int stq, int stk, int stv,
                      const float* __restrict__ bng, const float* __restrict__ bnb) {
    int gw = (blockIdx.x * blockDim.x + threadIdx.x) >> 5;
    int lane = threadIdx.x & 31;
    if (gw >= NN) return;
    int n = gw, f0 = lane, f1 = lane + 32;
    float2 q0 = bn_coef(stq, f0, bng + 4*HH, bnb + 4*HH);
    float2 q1 = bn_coef(stq, f1, bng + 4*HH, bnb + 4*HH);
    float2 k0 = bn_coef(stk, f0, bng + 5*HH, bnb + 5*HH);
    float2 k1 = bn_coef(stk, f1, bng + 5*HH, bnb + 5*HH);
    float2 v0 = bn_coef(stv, f0, bng + 6*HH, bnb + 6*HH);
    float2 v1 = bn_coef(stv, f1, bng + 6*HH, bnb + 6*HH);
    const float* Yq = g_buf[qIdx];
    const float* Yk = g_buf[kIdx];
    const float* Yv = g_buf[vIdx];
    unsigned qlo = __ballot_sync(0xffffffffu, fmaf(Yq[n*HH+f0], q0.x, q0.y) >= THV);
    unsigned qhi = __ballot_sync(0xffffffffu, fmaf(Yq[n*HH+f1], q1.x, q1.y) >= THV);
    unsigned klo = __ballot_sync(0xffffffffu, fmaf(Yk[n*HH+f0], k0.x, k0.y) >= THV);
    unsigned khi = __ballot_sync(0xffffffffu, fmaf(Yk[n*HH+f1], k1.x, k1.y) >= THV);
    unsigned vlo = __ballot_sync(0xffffffffu, fmaf(Yv[n*HH+f0], v0.x, v0.y) >= THV);
    unsigned vhi = __ballot_sync(0xffffffffu, fmaf(Yv[n*HH+f1], v1.x, v1.y) >= THV);
    int pc = __popc(qlo & klo) + __popc(qhi & khi);
    bool att = ((float)pc * (1.0f / 64.0f)) >= ATTV;
    if (lane == 0)
        g_bits[n] = att ? ((unsigned long long)vlo | ((unsigned long long)vhi << 32)) : 0ull;
}

// z[i] = sum_f bn(t2)[i,f] * wsum[f]
__global__ void k_dec(int tIdx, int st, const float* __restrict__ g,
                      const float* __restrict__ b, float* __restrict__ out) {
    int gw = (blockIdx.x * blockDim.x + threadIdx.x) >> 5;
    int lane = threadIdx.x & 31;
    if (gw >= NN) return;
    int n = gw, f0 = lane, f1 = lane + 32;
    float2 c0 = bn_coef(st, f0, g, b);
    float2 c1 = bn_coef(st, f1, g, b);
    const float* T = g_buf[tIdx];
    float w0 = g_wsum[f0], w1 = g_wsum[f1];
    float s = (fmaf(T[n*HH+f0], c0.x, c0.y)) * w0 + (fmaf(T[n*HH+f1], c1.x, c1.y)) * w1;
    #pragma unroll
    for (int o = 16; o > 0; o >>= 1) s += __shfl_down_sync(0xffffffffu, s, o);
    if (lane == 0) out[n] = s;
}

// ---------------- host orchestration ----------------
static void run_enc(int p, const float* Wg, const float* bg,
                    const float* bng, const float* bnb, float* out) {
    int base = 9 * p;
    const int T = 256;
    // conv0: agg already in buf[p]; GEMM -> buf2, stats base+0
    k_gemm<<<782, 128>>>(p, Wg + 0*HH*HH, bg + 0*HH, 2, base + 0);
    k_lif<<<WPN_BLOCKS, T>>>(2, base + 0, bng + 0*HH, bnb + 0*HH, -1);
    // conv1 on spikes
    k_aggbits<<<WPN_BLOCKS, T>>>(p, 5);
    k_gemm<<<782, 128>>>(5, Wg + 1*HH*HH, bg + 1*HH, 2, base + 1);
    k_bnspike<<<WPN_BLOCKS, T>>>(2, base + 1, bng + 1*HH, bnb + 1*HH, 3);  // x3 -> buf3
    // pos conv
    k_aggbits<<<WPN_BLOCKS, T>>>(p, 5);
    k_gemm<<<782, 128>>>(5, Wg + 2*HH*HH, bg + 2*HH, 2, base + 2);
    k_addstats<<<296, T>>>(2, base + 2, bng + 2*HH, bnb + 2*HH, 3, 1.0f, 4, base + 3); // t -> buf4
    k_lif<<<WPN_BLOCKS, T>>>(4, base + 3, bng + 3*HH, bnb + 3*HH, 4);  // x4 stored in buf4, att spikes
    // q/k/v share one aggregation
    k_aggbits<<<WPN_BLOCKS, T>>>(p, 5);
    k_gemm<<<782, 128>>>(5, Wg + 3*HH*HH, bg + 3*HH, 2, base + 4);  // Yq -> buf2
    k_gemm<<<782, 128>>>(5, Wg + 4*HH*HH, bg + 4*HH, 3, base + 5);  // Yk -> buf3
    k_gemm<<<782, 128>>>(5, Wg + 5*HH*HH, bg + 5*HH, 0, base + 6);  // Yv -> buf0
    k_qkv<<<WPN_BLOCKS, T>>>(2, 3, 0, base + 4, base + 5, base + 6, bng, bnb);
    // att conv
    k_aggbits<<<WPN_BLOCKS, T>>>(p, 5);
    k_gemm<<<782, 128>>>(5, Wg + 6*HH*HH, bg + 6*HH, 2, base + 7);
    k_addstats<<<296, T>>>(2, base + 7, bng + 7*HH, bnb + 7*HH, 4, 0.125f, 3, base + 8); // t2 -> buf3
    k_dec<<<WPN_BLOCKS, T>>>(3, base + 8, bng + 8*HH, bnb + 8*HH, out);
}

extern "C" void kernel_launch(void* const* d_in, const int* in_sizes, int n_in,
                              void* d_out, int out_size) {
    const float* x   = (const float*)d_in[0];
    const int*   ei  = (const int*)d_in[1];
    const int*   mk  = (const int*)d_in[2];
    const float* Wg  = (const float*)d_in[3];
    const float* bg  = (const float*)d_in[4];
    const float* bng = (const float*)d_in[5];
    const float* bnb = (const float*)d_in[6];
    const float* Wl  = (const float*)d_in[7];
    float* out = (float*)d_out;

    k_zero<<<25000, 256>>>();
    k_count<<<6250, 256>>>(ei, mk);
    k_scanA<<<SBLK, 1024>>>();
    k_scanB<<<1, 32>>>();
    k_scanC<<<391, 256>>>();
    k_scatter<<<6250, 256>>>(ei, mk);
    k_wsum<<<1, 64>>>(Wl);
    k_agg_dual<<<WPN_BLOCKS, 256>>>(x);  // conv0 aggregation, both passes

    run_enc(0, Wg, bg, bng, bnb, out);        // z1
    run_enc(1, Wg, bg, bng, bnb, out + NN);   // z2 (conv_lif V carries over)
}

// round 4
// speedup vs baseline: 1.0015x; 1.0015x over previous
#include <cuda_runtime.h>

#define NN 100000
#define EE 1600000
#define HH 64
#define THV 0.7f
#define ATTV 0.2f
#define EPSV 1e-5f
#define SBLK 98
#define WPN_BLOCKS 12500

__device__ float g_buf[6][NN*HH];
__device__ float g_V[NN*HH];
__device__ unsigned long long g_bits[NN];
__device__ int g_cnt1[NN], g_cnt2[NN];
__device__ int g_rowptr[NN+1], g_cursor[NN];
__device__ int4 g_er[EE];                 // {src, c1_bits, c2_bits, 0}
__device__ float g_dis1[NN], g_dis2[NN];
__device__ double g_stats[18][2][HH];
__device__ float g_wsum[HH];
__device__ int g_bsum[SBLK], g_boff[SBLK];

// ---------------- f32x2 helpers ----------------
__device__ __forceinline__ unsigned long long pk2(float x, float y) {
    unsigned long long r; asm("mov.b64 %0,{%1,%2};" : "=l"(r) : "f"(x), "f"(y)); return r;
}
__device__ __forceinline__ float2 up2(unsigned long long v) {
    float2 r; asm("mov.b64 {%0,%1},%2;" : "=f"(r.x), "=f"(r.y) : "l"(v)); return r;
}
__device__ __forceinline__ void fma2(unsigned long long& d, unsigned long long a, unsigned long long b) {
    asm("fma.rn.f32x2 %0,%1,%2,%0;" : "+l"(d) : "l"(a), "l"(b));
}

// ---------------- setup ----------------
__global__ void k_zero(const float* __restrict__ Wl) {
    int i = blockIdx.x * blockDim.x + threadIdx.x;
    if (i < NN*HH) g_V[i] = 0.f;
    if (i < NN) { g_cnt1[i] = 0; g_cnt2[i] = 0; }
    if (i < 18*2*HH) ((double*)g_stats)[i] = 0.0;
    if (i < HH) {
        float s = 0.f;
        for (int j = 0; j < HH; j++) s += Wl[i*HH + j];
        g_wsum[i] = s;
    }
}

__global__ void k_count(const int* __restrict__ ei, const int* __restrict__ mk) {
    int e = blockIdx.x * blockDim.x + threadIdx.x;
    if (e >= EE) return;
    int dst = ei[EE + e];
    atomicAdd(&g_cnt1[dst], 1);
    if (mk[e]) atomicAdd(&g_cnt2[dst], 1);
}

__global__ void k_scanA() {
    int t = threadIdx.x, b = blockIdx.x;
    int i = b * 1024 + t;
    int v = (i < NN) ? g_cnt1[i] : 0;
    int x = v;
    #pragma unroll
    for (int o = 1; o < 32; o <<= 1) {
        int y = __shfl_up_sync(0xffffffffu, x, o);
        if ((t & 31) >= o) x += y;
    }
    __shared__ int sw[32];
    if ((t & 31) == 31) sw[t >> 5] = x;
    __syncthreads();
    if (t < 32) {
        int y = sw[t], z = y;
        #pragma unroll
        for (int o = 1; o < 32; o <<= 1) {
            int w = __shfl_up_sync(0xffffffffu, z, o);
            if (t >= o) z += w;
        }
        sw[t] = z - y;
    }
    __syncthreads();
    int incl = x + sw[t >> 5];
    if (i < NN) g_rowptr[i] = incl - v;
    if (t == 1023) g_bsum[b] = incl;
}

__global__ void k_scanB() {
    int t = threadIdx.x;               // 128 threads
    int lane = t & 31, w = t >> 5;
    int v = (t < SBLK) ? g_bsum[t] : 0;
    int x = v;
    #pragma unroll
    for (int o = 1; o < 32; o <<= 1) {
        int y = __shfl_up_sync(0xffffffffu, x, o);
        if (lane >= o) x += y;
    }
    __shared__ int sw[4];
    if (lane == 31) sw[w] = x;
    __syncthreads();
    int add = 0;
    for (int j = 0; j < w; j++) add += sw[j];
    x += add;
    if (t < SBLK) g_boff[t] = x - v;
    if (t == SBLK - 1) g_rowptr[NN] = x;
}

__global__ void k_scanC() {
    int i = blockIdx.x * blockDim.x + threadIdx.x;
    if (i >= NN) return;
    int r = g_rowptr[i] + g_boff[i >> 10];
    g_rowptr[i] = r;
    g_cursor[i] = r;
    g_dis1[i] = rsqrtf(1.0f + (float)g_cnt1[i]);
    g_dis2[i] = rsqrtf(1.0f + (float)g_cnt2[i]);
}

__global__ void k_scatter(const int* __restrict__ ei, const int* __restrict__ mk) {
    int e = blockIdx.x * blockDim.x + threadIdx.x;
    if (e >= EE) return;
    int src = ei[e], dst = ei[EE + e];
    int m = mk[e];
    int p = atomicAdd(&g_cursor[dst], 1);
    float c1 = g_dis1[src] * g_dis1[dst];
    float c2 = m ? (g_dis2[src] * g_dis2[dst]) : 0.f;
    g_er[p] = make_int4(src, __float_as_int(c1), __float_as_int(c2), 0);
}

// ---------------- aggregations (broadcast direct-load, no SHFL) ----------------
__global__ void k_agg_dual(const float* __restrict__ x) {
    int gw = (blockIdx.x * blockDim.x + threadIdx.x) >> 5;
    int lane = threadIdx.x & 31;
    if (gw >= NN) return;
    int n = gw, f0 = lane, f1 = lane + 32;
    float d1 = g_dis1[n], d2 = g_dis2[n];
    float x0 = x[n*HH + f0], x1 = x[n*HH + f1];
    float a10 = d1*d1*x0, a11 = d1*d1*x1;
    float a20 = d2*d2*x0, a21 = d2*d2*x1;
    int s = g_rowptr[n], e = g_rowptr[n+1];
    int i = s;
    for (; i + 2 <= e; i += 2) {
        int4 r0 = g_er[i], r1 = g_er[i+1];
        float y00 = x[r0.x*HH + f0], y01 = x[r0.x*HH + f1];
        float y10 = x[r1.x*HH + f0], y11 = x[r1.x*HH + f1];
        float c10 = __int_as_float(r0.y), c20 = __int_as_float(r0.z);
        float c11 = __int_as_float(r1.y), c21 = __int_as_float(r1.z);
        a10 = fmaf(c10, y00, a10); a11 = fmaf(c10, y01, a11);
        a20 = fmaf(c20, y00, a20); a21 = fmaf(c20, y01, a21);
        a10 = fmaf(c11, y10, a10); a11 = fmaf(c11, y11, a11);
        a20 = fmaf(c21, y10, a20); a21 = fmaf(c21, y11, a21);
    }
    for (; i < e; i++) {
        int4 r = g_er[i];
        float y0 = x[r.x*HH + f0], y1 = x[r.x*HH + f1];
        float c1 = __int_as_float(r.y), c2 = __int_as_float(r.z);
        a10 = fmaf(c1, y0, a10); a11 = fmaf(c1, y1, a11);
        a20 = fmaf(c2, y0, a20); a21 = fmaf(c2, y1, a21);
    }
    g_buf[0][n*HH+f0] = a10; g_buf[0][n*HH+f1] = a11;
    g_buf[1][n*HH+f0] = a20; g_buf[1][n*HH+f1] = a21;
}

__global__ void k_aggbits(int pass, int outIdx) {
    int gw = (blockIdx.x * blockDim.x + threadIdx.x) >> 5;
    int lane = threadIdx.x & 31;
    if (gw >= NN) return;
    int n = gw;
    float d = pass ? g_dis2[n] : g_dis1[n];
    unsigned long long sb = g_bits[n];
    float self = d*d;
    float a0 = (((unsigned)sb        >> lane) & 1u) ? self : 0.f;
    float a1 = (((unsigned)(sb >> 32) >> lane) & 1u) ? self : 0.f;
    int s = g_rowptr[n], e = g_rowptr[n+1];
    int i = s;
    for (; i + 4 <= e; i += 4) {
        int4 r0 = g_er[i], r1 = g_er[i+1], r2 = g_er[i+2], r3 = g_er[i+3];
        unsigned long long b0 = g_bits[r0.x], b1 = g_bits[r1.x];
        unsigned long long b2 = g_bits[r2.x], b3 = g_bits[r3.x];
        float c0 = __int_as_float(pass ? r0.z : r0.y);
        float c1 = __int_as_float(pass ? r1.z : r1.y);
        float c2 = __int_as_float(pass ? r2.z : r2.y);
        float c3 = __int_as_float(pass ? r3.z : r3.y);
        a0 = fmaf(c0, (float)(((unsigned)b0 >> lane) & 1u), a0);
        a1 = fmaf(c0, (float)(((unsigned)(b0 >> 32) >> lane) & 1u), a1);
        a0 = fmaf(c1, (float)(((unsigned)b1 >> lane) & 1u), a0);
        a1 = fmaf(c1, (float)(((unsigned)(b1 >> 32) >> lane) & 1u), a1);
        a0 = fmaf(c2, (float)(((unsigned)b2 >> lane) & 1u), a0);
        a1 = fmaf(c2, (float)(((unsigned)(b2 >> 32) >> lane) & 1u), a1);
        a0 = fmaf(c3, (float)(((unsigned)b3 >> lane) & 1u), a0);
        a1 = fmaf(c3, (float)(((unsigned)(b3 >> 32) >> lane) & 1u), a1);
    }
    for (; i < e; i++) {
        int4 r = g_er[i];
        unsigned long long b = g_bits[r.x];
        float c = __int_as_float(pass ? r.z : r.y);
        a0 = fmaf(c, (float)(((unsigned)b >> lane) & 1u), a0);
        a1 = fmaf(c, (float)(((unsigned)(b >> 32) >> lane) & 1u), a1);
    }
    g_buf[outIdx][n*HH+lane]    = a0;
    g_buf[outIdx][n*HH+lane+32] = a1;
}

// ---------------- GEMM core (f32x2): Y = A@W + b, fused BN-stat accumulation ----
__device__ __forceinline__ void gemm_body(const float* __restrict__ A,
                                          const float* __restrict__ W,
                                          const float* __restrict__ bias,
                                          float* __restrict__ Y, int st,
                                          int base, int tid,
                                          float* As, float* Ws) {
    const float4* W4 = (const float4*)W;
    float4* Ws4 = (float4*)Ws;
    #pragma unroll
    for (int i = 0; i < 8; i++) Ws4[tid + 128*i] = W4[tid + 128*i];

    int row = base + tid;
    if (row < NN) {
        const float4* Ar = (const float4*)(A + row*HH);
        #pragma unroll
        for (int v = 0; v < 16; v++) {
            float4 q = Ar[v];
            As[(4*v+0)*128 + tid] = q.x; As[(4*v+1)*128 + tid] = q.y;
            As[(4*v+2)*128 + tid] = q.z; As[(4*v+3)*128 + tid] = q.w;
        }
    } else {
        #pragma unroll
        for (int v = 0; v < 64; v++) As[v*128 + tid] = 0.f;
    }
    __syncthreads();

    int cx = tid & 7, ry = tid >> 3;
    unsigned long long acc[4][8];
    #pragma unroll
    for (int p = 0; p < 4; p++)
        #pragma unroll
        for (int c = 0; c < 8; c++) acc[p][c] = 0ull;

    #pragma unroll 2
    for (int k = 0; k < 64; k++) {
        const float* ap = &As[k*128 + 8*ry];
        unsigned long long a0 = *(const unsigned long long*)(ap);
        unsigned long long a1 = *(const unsigned long long*)(ap + 2);
        unsigned long long a2 = *(const unsigned long long*)(ap + 4);
        unsigned long long a3 = *(const unsigned long long*)(ap + 6);
        float4 w0 = *(const float4*)&Ws[k*64 + 8*cx];
        float4 w1 = *(const float4*)&Ws[k*64 + 8*cx + 4];
        unsigned long long wd[8];
        wd[0] = pk2(w0.x, w0.x); wd[1] = pk2(w0.y, w0.y);
        wd[2] = pk2(w0.z, w0.z); wd[3] = pk2(w0.w, w0.w);
        wd[4] = pk2(w1.x, w1.x); wd[5] = pk2(w1.y, w1.y);
        wd[6] = pk2(w1.z, w1.z); wd[7] = pk2(w1.w, w1.w);
        #pragma unroll
        for (int c = 0; c < 8; c++) {
            fma2(acc[0][c], a0, wd[c]);
            fma2(acc[1][c], a1, wd[c]);
            fma2(acc[2][c], a2, wd[c]);
            fma2(acc[3][c], a3, wd[c]);
        }
    }

    __syncthreads();
    float* ssum = Ws;
    float* ssq  = Ws + 64;
    if (tid < 64) { ssum[tid] = 0.f; ssq[tid] = 0.f; }
    __syncthreads();

    float b8[8];
    #pragma unroll
    for (int c = 0; c < 8; c++) b8[c] = bias[8*cx + c];
    float ls[8], lq[8];
    #pragma unroll
    for (int c = 0; c < 8; c++) { ls[c] = 0.f; lq[c] = 0.f; }

    #pragma unroll
    for (int p = 0; p < 4; p++) {
        float vlo[8], vhi[8];
        #pragma unroll
        for (int c = 0; c < 8; c++) {
            float2 t = up2(acc[p][c]);
            vlo[c] = t.x + b8[c];
            vhi[c] = t.y + b8[c];
        }
        int r0 = base + 8*ry + 2*p, r1 = r0 + 1;
        if (r0 < NN) {
            #pragma unroll
            for (int c = 0; c < 8; c++) { ls[c] += vlo[c]; lq[c] = fmaf(vlo[c], vlo[c], lq[c]); }
            *(float4*)&Y[r0*HH + 8*cx]     = make_float4(vlo[0],vlo[1],vlo[2],vlo[3]);
            *(float4*)&Y[r0*HH + 8*cx + 4] = make_float4(vlo[4],vlo[5],vlo[6],vlo[7]);
        }
        if (r1 < NN) {
            #pragma unroll
            for (int c = 0; c < 8; c++) { ls[c] += vhi[c]; lq[c] = fmaf(vhi[c], vhi[c], lq[c]); }
            *(float4*)&Y[r1*HH + 8*cx]     = make_float4(vhi[0],vhi[1],vhi[2],vhi[3]);
            *(float4*)&Y[r1*HH + 8*cx + 4] = make_float4(vhi[4],vhi[5],vhi[6],vhi[7]);
        }
    }
    #pragma unroll
    for (int c = 0; c < 8; c++) {
        atomicAdd(&ssum[8*cx + c], ls[c]);
        atomicAdd(&ssq[8*cx + c],  lq[c]);
    }
    __syncthreads();
    if (tid < 64) {
        atomicAdd(&g_stats[st][0][tid], (double)ssum[tid]);
        atomicAdd(&g_stats[st][1][tid], (double)ssq[tid]);
    }
}

__global__ void __launch_bounds__(128) k_gemm(int aIdx, const float* __restrict__ W,
                                              const float* __restrict__ bias,
                                              int yIdx, int st) {
    __shared__ float As[64*128];
    __shared__ float Ws[64*64];
    gemm_body(g_buf[aIdx], W, bias, g_buf[yIdx], st, blockIdx.x * 128, threadIdx.x, As, Ws);
}

__global__ void __launch_bounds__(128) k_gemmQKV(const float* __restrict__ Wg,
                                                 const float* __restrict__ bg, int stBase) {
    __shared__ float As[64*128];
    __shared__ float Ws[64*64];
    int y = blockIdx.y;
    int outIdx = (y == 0) ? 2 : (y == 1) ? 3 : 0;
    gemm_body(g_buf[5], Wg + (3+y)*HH*HH, bg + (3+y)*HH, g_buf[outIdx],
              stBase + y, blockIdx.x * 128, threadIdx.x, As, Ws);
}

// ---------------- BN helper ----------------
__device__ __forceinline__ float2 bn_coef(int st, int f, const float* __restrict__ g,
                                          const float* __restrict__ b) {
    double s = g_stats[st][0][f], q = g_stats[st][1][f];
    double mean = s * (1.0 / NN);
    float var = (float)(q * (1.0 / NN) - mean * mean);
    float rstd = rsqrtf(var + EPSV);
    float sc = g[f] * rstd;
    float sh = b[f] - (float)mean * sc;
    return make_float2(sc, sh);
}

__global__ void k_lif(int yIdx, int st, const float* __restrict__ g,
                      const float* __restrict__ b, int storeIdx) {
    int gw = (blockIdx.x * blockDim.x + threadIdx.x) >> 5;
    int lane = threadIdx.x & 31;
    if (gw >= NN) return;
    int n = gw, f0 = lane, f1 = lane + 32;
    float2 c0 = bn_coef(st, f0, g, b);
    float2 c1 = bn_coef(st, f1, g, b);
    const float* Y = g_buf[yIdx];
    float x0 = fmaf(Y[n*HH+f0], c0.x, c0.y);
    float x1 = fmaf(Y[n*HH+f1], c1.x, c1.y);
    if (storeIdx >= 0) { g_buf[storeIdx][n*HH+f0] = x0; g_buf[storeIdx][n*HH+f1] = x1; }
    float v0 = g_V[n*HH+f0] + x0;
    float v1 = g_V[n*HH+f1] + x1;
    bool s0 = v0 >= THV, s1 = v1 >= THV;
    g_V[n*HH+f0] = s0 ? 0.f : v0;
    g_V[n*HH+f1] = s1 ? 0.f : v1;
    unsigned lo = __ballot_sync(0xffffffffu, s0);
    unsigned hi = __ballot_sync(0xffffffffu, s1);
    if (lane == 0) g_bits[n] = (unsigned long long)lo | ((unsigned long long)hi << 32);
}

__global__ void k_bnspike(int yIdx, int st, const float* __restrict__ g,
                          const float* __restrict__ b, int storeIdx) {
    int gw = (blockIdx.x * blockDim.x + threadIdx.x) >> 5;
    int lane = threadIdx.x & 31;
    if (gw >= NN) return;
    int n = gw, f0 = lane, f1 = lane + 32;
    float2 c0 = bn_coef(st, f0, g, b);
    float2 c1 = bn_coef(st, f1, g, b);
    const float* Y = g_buf[yIdx];
    float x0 = fmaf(Y[n*HH+f0], c0.x, c0.y);
    float x1 = fmaf(Y[n*HH+f1], c1.x, c1.y);
    g_buf[storeIdx][n*HH+f0] = x0;
    g_buf[storeIdx][n*HH+f1] = x1;
    unsigned lo = __ballot_sync(0xffffffffu, x0 >= THV);
    unsigned hi = __ballot_sync(0xffffffffu, x1 >= THV);
    if (lane == 0) g_bits[n] = (unsigned long long)lo | ((unsigned long long)hi << 32);
}

__global__ void k_addstats(int yIdx, int st, const float* __restrict__ g,
                           const float* __restrict__ b, int addIdx, float scale,
                           int outIdx, int stOut) {
    int lane = threadIdx.x & 31;
    int wid = (blockIdx.x * blockDim.x + threadIdx.x) >> 5;
    int nw = (gridDim.x * blockDim.x) >> 5;
    int f0 = lane, f1 = lane + 32;
    float2 c0 = bn_coef(st, f0, g, b);
    float2 c1 = bn_coef(st, f1, g, b);
    const float* Y = g_buf[yIdx];
    const float* Ad = g_buf[addIdx];
    float* O = g_buf[outIdx];
    float ls0 = 0.f, lq0 = 0.f, ls1 = 0.f, lq1 = 0.f;
    for (int n = wid; n < NN; n += nw) {
        float t0 = fmaf(scale, fmaf(Y[n*HH+f0], c0.x, c0.y), Ad[n*HH+f0]);
        float t1 = fmaf(scale, fmaf(Y[n*HH+f1], c1.x, c1.y), Ad[n*HH+f1]);
        O[n*HH+f0] = t0; O[n*HH+f1] = t1;
        ls0 += t0; lq0 = fmaf(t0, t0, lq0);
        ls1 += t1; lq1 = fmaf(t1, t1, lq1);
    }
    __shared__ float ss[64], sq[64];
    if (threadIdx.x < 64) { ss[threadIdx.x] = 0.f; sq[threadIdx.x] = 0.f; }
    __syncthreads();
    atomicAdd(&ss[f0], ls0); atomicAdd(&sq[f0], lq0);
    atomicAdd(&ss[f1], ls1); atomicAdd(&sq[f1], lq1);
    __syncthreads();
    if (threadIdx.x < 64) {
        atomicAdd(&g_stats[stOut][0][threadIdx.x], (double)ss[threadIdx.x]);
        atomicAdd(&g_stats[stOut][1][threadIdx.x], (double)sq[threadIdx.x]);
    }
}

__global__ void k_qkv(int qIdx, int kIdx, int vIdx, int stq, int stk, int stv,
                      const float* __restrict__ bng, const float* __restrict__ bnb) {
    int gw = (blockIdx.x * blockDim.x + threadIdx.x) >> 5;
    int lane = threadIdx.x & 31;
    if (gw >= NN) return;
    int n = gw, f0 = lane, f1 = lane + 32;
    float2 q0 = bn_coef(stq, f0, bng + 4*HH, bnb + 4*HH);
    float2 q1 = bn_coef(stq, f1, bng + 4*HH, bnb + 4*HH);
    float2 k0 = bn_coef(stk, f0, bng + 5*HH, bnb + 5*HH);
    float2 k1 = bn_coef(stk, f1, bng + 5*HH, bnb + 5*HH);
    float2 v0 = bn_coef(stv, f0, bng + 6*HH, bnb + 6*HH);
    float2 v1 = bn_coef(stv, f1, bng + 6*HH, bnb + 6*HH);
    const float* Yq = g_buf[qIdx];
    const float* Yk = g_buf[kIdx];
    const float* Yv = g_buf[vIdx];
    unsigned qlo = __ballot_sync(0xffffffffu, fmaf(Yq[n*HH+f0], q0.x, q0.y) >= THV);
    unsigned qhi = __ballot_sync(0xffffffffu, fmaf(Yq[n*HH+f1], q1.x, q1.y) >= THV);
    unsigned klo = __ballot_sync(0xffffffffu, fmaf(Yk[n*HH+f0], k0.x, k0.y) >= THV);
    unsigned khi = __ballot_sync(0xffffffffu, fmaf(Yk[n*HH+f1], k1.x, k1.y) >= THV);
    unsigned vlo = __ballot_sync(0xffffffffu, fmaf(Yv[n*HH+f0], v0.x, v0.y) >= THV);
    unsigned vhi = __ballot_sync(0xffffffffu, fmaf(Yv[n*HH+f1], v1.x, v1.y) >= THV);
    int pc = __popc(qlo & klo) + __popc(qhi & khi);
    bool att = ((float)pc * (1.0f / 64.0f)) >= ATTV;
    if (lane == 0)
        g_bits[n] = att ? ((unsigned long long)vlo | ((unsigned long long)vhi << 32)) : 0ull;
}

__global__ void k_dec(int tIdx, int st, const float* __restrict__ g,
                      const float* __restrict__ b, float* __restrict__ out) {
    int gw = (blockIdx.x * blockDim.x + threadIdx.x) >> 5;
    int lane = threadIdx.x & 31;
    if (gw >= NN) return;
    int n = gw, f0 = lane, f1 = lane + 32;
    float2 c0 = bn_coef(st, f0, g, b);
    float2 c1 = bn_coef(st, f1, g, b);
    const float* T = g_buf[tIdx];
    float w0 = g_wsum[f0], w1 = g_wsum[f1];
    float s = (fmaf(T[n*HH+f0], c0.x, c0.y)) * w0 + (fmaf(T[n*HH+f1], c1.x, c1.y)) * w1;
    #pragma unroll
    for (int o = 16; o > 0; o >>= 1) s += __shfl_down_sync(0xffffffffu, s, o);
    if (lane == 0) out[n] = s;
}

// ---------------- host orchestration ----------------
static void run_enc(int p, const float* Wg, const float* bg,
                    const float* bng, const float* bnb, float* out) {
    int base = 9 * p;
    const int T = 256;
    k_gemm<<<782, 128>>>(p, Wg + 0*HH*HH, bg + 0*HH, 2, base + 0);
    k_lif<<<WPN_BLOCKS, T>>>(2, base + 0, bng + 0*HH, bnb + 0*HH, -1);
    k_aggbits<<<WPN_BLOCKS, T>>>(p, 5);
    k_gemm<<<782, 128>>>(5, Wg + 1*HH*HH, bg + 1*HH, 2, base + 1);
    k_bnspike<<<WPN_BLOCKS, T>>>(2, base + 1, bng + 1*HH, bnb + 1*HH, 3);
    k_aggbits<<<WPN_BLOCKS, T>>>(p, 5);
    k_gemm<<<782, 128>>>(5, Wg + 2*HH*HH, bg + 2*HH, 2, base + 2);
    k_addstats<<<296, T>>>(2, base + 2, bng + 2*HH, bnb + 2*HH, 3, 1.0f, 4, base + 3);
    k_lif<<<WPN_BLOCKS, T>>>(4, base + 3, bng + 3*HH, bnb + 3*HH, 4);
    k_aggbits<<<WPN_BLOCKS, T>>>(p, 5);
    k_gemmQKV<<<dim3(782, 3), 128>>>(Wg, bg, base + 4);
    k_qkv<<<WPN_BLOCKS, T>>>(2, 3, 0, base + 4, base + 5, base + 6, bng, bnb);
    k_aggbits<<<WPN_BLOCKS, T>>>(p, 5);
    k_gemm<<<782, 128>>>(5, Wg + 6*HH*HH, bg + 6*HH, 2, base + 7);
    k_addstats<<<296, T>>>(2, base + 7, bng + 7*HH, bnb + 7*HH, 4, 0.125f, 3, base + 8);
    k_dec<<<WPN_BLOCKS, T>>>(3, base + 8, bng + 8*HH, bnb + 8*HH, out);
}

extern "C" void kernel_launch(void* const* d_in, const int* in_sizes, int n_in,
                              void* d_out, int out_size) {
    const float* x   = (const float*)d_in[0];
    const int*   ei  = (const int*)d_in[1];
    const int*   mk  = (const int*)d_in[2];
    const float* Wg  = (const float*)d_in[3];
    const float* bg  = (const float*)d_in[4];
    const float* bng = (const float*)d_in[5];
    const float* bnb = (const float*)d_in[6];
    const float* Wl  = (const float*)d_in[7];
    float* out = (float*)d_out;

    k_zero<<<25000, 256>>>(Wl);
    k_count<<<6250, 256>>>(ei, mk);
    k_scanA<<<SBLK, 1024>>>();
    k_scanB<<<1, 128>>>();
    k_scanC<<<391, 256>>>();
    k_scatter<<<6250, 256>>>(ei, mk);
    k_agg_dual<<<WPN_BLOCKS, 256>>>(x);

    run_enc(0, Wg, bg, bng, bnb, out);
    run_enc(1, Wg, bg, bng, bnb, out + NN);
}

// round 5
// speedup vs baseline: 1.5478x; 1.5455x over previous
#include <cuda_runtime.h>

#define NN 100000
#define EE 1600000
#define HH 64
#define THV 0.7f
#define ATTV 0.2f
#define EPSV 1e-5f
#define SBLK 98
#define EB 1184          // one-wave grid for elementwise/agg kernels

__device__ float g_buf[6][NN*HH];
__device__ float g_V[NN*HH];
__device__ unsigned long long g_bits[NN];
__device__ int g_cnt1[NN], g_cnt2[NN];
__device__ int g_rowptr[NN+1], g_cursor[NN];
__device__ int4 g_er[EE];                 // {src, c1_bits, c2_bits, 0}
__device__ float g_dis1[NN], g_dis2[NN];
__device__ double g_stats[18][2][HH];
__device__ float g_wsum[HH];
__device__ int g_bsum[SBLK];

// ---------------- f32x2 helpers ----------------
__device__ __forceinline__ unsigned long long pk2(float x, float y) {
    unsigned long long r; asm("mov.b64 %0,{%1,%2};" : "=l"(r) : "f"(x), "f"(y)); return r;
}
__device__ __forceinline__ float2 up2(unsigned long long v) {
    float2 r; asm("mov.b64 {%0,%1},%2;" : "=f"(r.x), "=f"(r.y) : "l"(v)); return r;
}
__device__ __forceinline__ void fma2(unsigned long long& d, unsigned long long a, unsigned long long b) {
    asm("fma.rn.f32x2 %0,%1,%2,%0;" : "+l"(d) : "l"(a), "l"(b));
}

// ---------------- setup ----------------
__global__ void k_zero(const float* __restrict__ Wl) {
    int stride = gridDim.x * blockDim.x;
    for (int i = blockIdx.x * blockDim.x + threadIdx.x; i < NN*HH; i += stride) {
        g_V[i] = 0.f;
        if (i < NN) { g_cnt1[i] = 0; g_cnt2[i] = 0; }
        if (i < 18*2*HH) ((double*)g_stats)[i] = 0.0;
        if (i < HH) {
            float s = 0.f;
            for (int j = 0; j < HH; j++) s += Wl[i*HH + j];
            g_wsum[i] = s;
        }
    }
}

__global__ void k_count(const int* __restrict__ ei, const int* __restrict__ mk) {
    int stride = gridDim.x * blockDim.x;
    for (int e = blockIdx.x * blockDim.x + threadIdx.x; e < EE; e += stride) {
        int dst = ei[EE + e];
        atomicAdd(&g_cnt1[dst], 1);
        if (mk[e]) atomicAdd(&g_cnt2[dst], 1);
    }
}

__global__ void k_scanA() {
    int t = threadIdx.x, b = blockIdx.x;
    int i = b * 1024 + t;
    int v = (i < NN) ? g_cnt1[i] : 0;
    int x = v;
    #pragma unroll
    for (int o = 1; o < 32; o <<= 1) {
        int y = __shfl_up_sync(0xffffffffu, x, o);
        if ((t & 31) >= o) x += y;
    }
    __shared__ int sw[32];
    if ((t & 31) == 31) sw[t >> 5] = x;
    __syncthreads();
    if (t < 32) {
        int y = sw[t], z = y;
        #pragma unroll
        for (int o = 1; o < 32; o <<= 1) {
            int w = __shfl_up_sync(0xffffffffu, z, o);
            if (t >= o) z += w;
        }
        sw[t] = z - y;
    }
    __syncthreads();
    int incl = x + sw[t >> 5];
    if (i < NN) g_rowptr[i] = incl - v;
    if (t == 1023) g_bsum[b] = incl;
}

// folded scanB: each block prefixes the 98 block sums from smem (redundant, cheap)
__global__ void k_scanC() {
    __shared__ int sb[SBLK];
    int t = threadIdx.x;
    if (t < SBLK) sb[t] = g_bsum[t];
    __syncthreads();
    int i = blockIdx.x * 256 + t;
    int chunk = i >> 10;              // constant within a 256-thread block
    int off = 0;
    for (int j = 0; j < chunk; j++) off += sb[j];
    if (i < NN) {
        int r = g_rowptr[i] + off;
        g_rowptr[i] = r;
        g_cursor[i] = r;
        g_dis1[i] = rsqrtf(1.0f + (float)g_cnt1[i]);
        g_dis2[i] = rsqrtf(1.0f + (float)g_cnt2[i]);
    }
    if (blockIdx.x == 390 && t == 0) {
        int tot = 0;
        for (int j = 0; j < SBLK; j++) tot += sb[j];
        g_rowptr[NN] = tot;
    }
}

__global__ void k_scatter(const int* __restrict__ ei, const int* __restrict__ mk) {
    int stride = gridDim.x * blockDim.x;
    for (int e = blockIdx.x * blockDim.x + threadIdx.x; e < EE; e += stride) {
        int src = ei[e], dst = ei[EE + e];
        int m = mk[e];
        int p = atomicAdd(&g_cursor[dst], 1);
        float c1 = g_dis1[src] * g_dis1[dst];
        float c2 = m ? (g_dis2[src] * g_dis2[dst]) : 0.f;
        g_er[p] = make_int4(src, __float_as_int(c1), __float_as_int(c2), 0);
    }
}

// ---------------- aggregations (grid-stride warp-per-node) ----------------
__global__ void k_agg_dual(const float* __restrict__ x) {
    int lane = threadIdx.x & 31;
    int w0id = (blockIdx.x * blockDim.x + threadIdx.x) >> 5;
    int nw = (gridDim.x * blockDim.x) >> 5;
    int f0 = lane, f1 = lane + 32;
    for (int n = w0id; n < NN; n += nw) {
        float d1 = g_dis1[n], d2 = g_dis2[n];
        float x0 = x[n*HH + f0], x1 = x[n*HH + f1];
        float a10 = d1*d1*x0, a11 = d1*d1*x1;
        float a20 = d2*d2*x0, a21 = d2*d2*x1;
        int s = g_rowptr[n], e = g_rowptr[n+1];
        int i = s;
        for (; i + 2 <= e; i += 2) {
            int4 r0 = g_er[i], r1 = g_er[i+1];
            float y00 = x[r0.x*HH + f0], y01 = x[r0.x*HH + f1];
            float y10 = x[r1.x*HH + f0], y11 = x[r1.x*HH + f1];
            float c10 = __int_as_float(r0.y), c20 = __int_as_float(r0.z);
            float c11 = __int_as_float(r1.y), c21 = __int_as_float(r1.z);
            a10 = fmaf(c10, y00, a10); a11 = fmaf(c10, y01, a11);
            a20 = fmaf(c20, y00, a20); a21 = fmaf(c20, y01, a21);
            a10 = fmaf(c11, y10, a10); a11 = fmaf(c11, y11, a11);
            a20 = fmaf(c21, y10, a20); a21 = fmaf(c21, y11, a21);
        }
        for (; i < e; i++) {
            int4 r = g_er[i];
            float y0 = x[r.x*HH + f0], y1 = x[r.x*HH + f1];
            float c1 = __int_as_float(r.y), c2 = __int_as_float(r.z);
            a10 = fmaf(c1, y0, a10); a11 = fmaf(c1, y1, a11);
            a20 = fmaf(c2, y0, a20); a21 = fmaf(c2, y1, a21);
        }
        g_buf[0][n*HH+f0] = a10; g_buf[0][n*HH+f1] = a11;
        g_buf[1][n*HH+f0] = a20; g_buf[1][n*HH+f1] = a21;
    }
}

__global__ void k_aggbits(int pass, int outIdx) {
    int lane = threadIdx.x & 31;
    int w0id = (blockIdx.x * blockDim.x + threadIdx.x) >> 5;
    int nw = (gridDim.x * blockDim.x) >> 5;
    for (int n = w0id; n < NN; n += nw) {
        float d = pass ? g_dis2[n] : g_dis1[n];
        unsigned long long sb = g_bits[n];
        float self = d*d;
        float a0 = (((unsigned)sb        >> lane) & 1u) ? self : 0.f;
        float a1 = (((unsigned)(sb >> 32) >> lane) & 1u) ? self : 0.f;
        int s = g_rowptr[n], e = g_rowptr[n+1];
        int i = s;
        for (; i + 4 <= e; i += 4) {
            int4 r0 = g_er[i], r1 = g_er[i+1], r2 = g_er[i+2], r3 = g_er[i+3];
            unsigned long long b0 = g_bits[r0.x], b1 = g_bits[r1.x];
            unsigned long long b2 = g_bits[r2.x], b3 = g_bits[r3.x];
            float c0 = __int_as_float(pass ? r0.z : r0.y);
            float c1 = __int_as_float(pass ? r1.z : r1.y);
            float c2 = __int_as_float(pass ? r2.z : r2.y);
            float c3 = __int_as_float(pass ? r3.z : r3.y);
            a0 = fmaf(c0, (float)(((unsigned)b0 >> lane) & 1u), a0);
            a1 = fmaf(c0, (float)(((unsigned)(b0 >> 32) >> lane) & 1u), a1);
            a0 = fmaf(c1, (float)(((unsigned)b1 >> lane) & 1u), a0);
            a1 = fmaf(c1, (float)(((unsigned)(b1 >> 32) >> lane) & 1u), a1);
            a0 = fmaf(c2, (float)(((unsigned)b2 >> lane) & 1u), a0);
            a1 = fmaf(c2, (float)(((unsigned)(b2 >> 32) >> lane) & 1u), a1);
            a0 = fmaf(c3, (float)(((unsigned)b3 >> lane) & 1u), a0);
            a1 = fmaf(c3, (float)(((unsigned)(b3 >> 32) >> lane) & 1u), a1);
        }
        for (; i < e; i++) {
            int4 r = g_er[i];
            unsigned long long b = g_bits[r.x];
            float c = __int_as_float(pass ? r.z : r.y);
            a0 = fmaf(c, (float)(((unsigned)b >> lane) & 1u), a0);
            a1 = fmaf(c, (float)(((unsigned)(b >> 32) >> lane) & 1u), a1);
        }
        g_buf[outIdx][n*HH+lane]    = a0;
        g_buf[outIdx][n*HH+lane+32] = a1;
    }
}

// ---------------- GEMM core (f32x2), 2 tiles per block ----------------
__device__ __forceinline__ void gemm_body(const float* __restrict__ A,
                                          const float* __restrict__ W,
                                          const float* __restrict__ bias,
                                          float* __restrict__ Y, int st,
                                          int tid, float* As, float* Ws) {
    const float4* W4 = (const float4*)W;
    float4* Ws4 = (float4*)Ws;
    #pragma unroll
    for (int i = 0; i < 8; i++) Ws4[tid + 128*i] = W4[tid + 128*i];

    int cx = tid & 7, ry = tid >> 3;
    float b8[8];
    #pragma unroll
    for (int c = 0; c < 8; c++) b8[c] = bias[8*cx + c];
    float ls[8], lq[8];
    #pragma unroll
    for (int c = 0; c < 8; c++) { ls[c] = 0.f; lq[c] = 0.f; }

    #pragma unroll 1
    for (int t = 0; t < 2; t++) {
        int base = (blockIdx.x * 2 + t) * 128;
        __syncthreads();
        int row = base + tid;
        if (row < NN) {
            const float4* Ar = (const float4*)(A + row*HH);
            #pragma unroll
            for (int v = 0; v < 16; v++) {
                float4 q = Ar[v];
                As[(4*v+0)*128 + tid] = q.x; As[(4*v+1)*128 + tid] = q.y;
                As[(4*v+2)*128 + tid] = q.z; As[(4*v+3)*128 + tid] = q.w;
            }
        } else {
            #pragma unroll
            for (int v = 0; v < 64; v++) As[v*128 + tid] = 0.f;
        }
        __syncthreads();

        unsigned long long acc[4][8];
        #pragma unroll
        for (int p = 0; p < 4; p++)
            #pragma unroll
            for (int c = 0; c < 8; c++) acc[p][c] = 0ull;

        #pragma unroll 2
        for (int k = 0; k < 64; k++) {
            const float* ap = &As[k*128 + 8*ry];
            unsigned long long a0 = *(const unsigned long long*)(ap);
            unsigned long long a1 = *(const unsigned long long*)(ap + 2);
            unsigned long long a2 = *(const unsigned long long*)(ap + 4);
            unsigned long long a3 = *(const unsigned long long*)(ap + 6);
            float4 w0 = *(const float4*)&Ws[k*64 + 8*cx];
            float4 w1 = *(const float4*)&Ws[k*64 + 8*cx + 4];
            unsigned long long wd[8];
            wd[0] = pk2(w0.x, w0.x); wd[1] = pk2(w0.y, w0.y);
            wd[2] = pk2(w0.z, w0.z); wd[3] = pk2(w0.w, w0.w);
            wd[4] = pk2(w1.x, w1.x); wd[5] = pk2(w1.y, w1.y);
            wd[6] = pk2(w1.z, w1.z); wd[7] = pk2(w1.w, w1.w);
            #pragma unroll
            for (int c = 0; c < 8; c++) {
                fma2(acc[0][c], a0, wd[c]);
                fma2(acc[1][c], a1, wd[c]);
                fma2(acc[2][c], a2, wd[c]);
                fma2(acc[3][c], a3, wd[c]);
            }
        }

        #pragma unroll
        for (int p = 0; p < 4; p++) {
            float vlo[8], vhi[8];
            #pragma unroll
            for (int c = 0; c < 8; c++) {
                float2 tt = up2(acc[p][c]);
                vlo[c] = tt.x + b8[c];
                vhi[c] = tt.y + b8[c];
            }
            int r0 = base + 8*ry + 2*p, r1 = r0 + 1;
            if (r0 < NN) {
                #pragma unroll
                for (int c = 0; c < 8; c++) { ls[c] += vlo[c]; lq[c] = fmaf(vlo[c], vlo[c], lq[c]); }
                *(float4*)&Y[r0*HH + 8*cx]     = make_float4(vlo[0],vlo[1],vlo[2],vlo[3]);
                *(float4*)&Y[r0*HH + 8*cx + 4] = make_float4(vlo[4],vlo[5],vlo[6],vlo[7]);
            }
            if (r1 < NN) {
                #pragma unroll
                for (int c = 0; c < 8; c++) { ls[c] += vhi[c]; lq[c] = fmaf(vhi[c], vhi[c], lq[c]); }
                *(float4*)&Y[r1*HH + 8*cx]     = make_float4(vhi[0],vhi[1],vhi[2],vhi[3]);
                *(float4*)&Y[r1*HH + 8*cx + 4] = make_float4(vhi[4],vhi[5],vhi[6],vhi[7]);
            }
        }
    }

    __syncthreads();
    float* ssum = As;
    float* ssq  = As + 64;
    if (tid < 64) { ssum[tid] = 0.f; ssq[tid] = 0.f; }
    __syncthreads();
    #pragma unroll
    for (int c = 0; c < 8; c++) {
        atomicAdd(&ssum[8*cx + c], ls[c]);
        atomicAdd(&ssq[8*cx + c],  lq[c]);
    }
    __syncthreads();
    if (tid < 64) {
        atomicAdd(&g_stats[st][0][tid], (double)ssum[tid]);
        atomicAdd(&g_stats[st][1][tid], (double)ssq[tid]);
    }
}

__global__ void __launch_bounds__(128) k_gemm(int aIdx, const float* __restrict__ W,
                                              const float* __restrict__ bias,
                                              int yIdx, int st) {
    __shared__ float As[64*128];
    __shared__ float Ws[64*64];
    gemm_body(g_buf[aIdx], W, bias, g_buf[yIdx], st, threadIdx.x, As, Ws);
}

__global__ void __launch_bounds__(128) k_gemmQKV(const float* __restrict__ Wg,
                                                 const float* __restrict__ bg, int stBase) {
    __shared__ float As[64*128];
    __shared__ float Ws[64*64];
    int y = blockIdx.y;
    int outIdx = (y == 0) ? 2 : (y == 1) ? 3 : 0;
    gemm_body(g_buf[5], Wg + (3+y)*HH*HH, bg + (3+y)*HH, g_buf[outIdx],
              stBase + y, threadIdx.x, As, Ws);
}

// ---------------- BN helper ----------------
__device__ __forceinline__ float2 bn_coef(int st, int f, const float* __restrict__ g,
                                          const float* __restrict__ b) {
    double s = g_stats[st][0][f], q = g_stats[st][1][f];
    double mean = s * (1.0 / NN);
    float var = (float)(q * (1.0 / NN) - mean * mean);
    float rstd = rsqrtf(var + EPSV);
    float sc = g[f] * rstd;
    float sh = b[f] - (float)mean * sc;
    return make_float2(sc, sh);
}

// grid-stride: coefs hoisted once per warp
__global__ void k_lif(int yIdx, int st, const float* __restrict__ g,
                      const float* __restrict__ b, int storeIdx) {
    int lane = threadIdx.x & 31;
    int wid = (blockIdx.x * blockDim.x + threadIdx.x) >> 5;
    int nw = (gridDim.x * blockDim.x) >> 5;
    int f0 = lane, f1 = lane + 32;
    float2 c0 = bn_coef(st, f0, g, b);
    float2 c1 = bn_coef(st, f1, g, b);
    const float* Y = g_buf[yIdx];
    for (int n = wid; n < NN; n += nw) {
        float x0 = fmaf(Y[n*HH+f0], c0.x, c0.y);
        float x1 = fmaf(Y[n*HH+f1], c1.x, c1.y);
        if (storeIdx >= 0) { g_buf[storeIdx][n*HH+f0] = x0; g_buf[storeIdx][n*HH+f1] = x1; }
        float v0 = g_V[n*HH+f0] + x0;
        float v1 = g_V[n*HH+f1] + x1;
        bool s0 = v0 >= THV, s1 = v1 >= THV;
        g_V[n*HH+f0] = s0 ? 0.f : v0;
        g_V[n*HH+f1] = s1 ? 0.f : v1;
        unsigned lo = __ballot_sync(0xffffffffu, s0);
        unsigned hi = __ballot_sync(0xffffffffu, s1);
        if (lane == 0) g_bits[n] = (unsigned long long)lo | ((unsigned long long)hi << 32);
    }
}

__global__ void k_bnspike(int yIdx, int st, const float* __restrict__ g,
                          const float* __restrict__ b, int storeIdx) {
    int lane = threadIdx.x & 31;
    int wid = (blockIdx.x * blockDim.x + threadIdx.x) >> 5;
    int nw = (gridDim.x * blockDim.x) >> 5;
    int f0 = lane, f1 = lane + 32;
    float2 c0 = bn_coef(st, f0, g, b);
    float2 c1 = bn_coef(st, f1, g, b);
    const float* Y = g_buf[yIdx];
    for (int n = wid; n < NN; n += nw) {
        float x0 = fmaf(Y[n*HH+f0], c0.x, c0.y);
        float x1 = fmaf(Y[n*HH+f1], c1.x, c1.y);
        g_buf[storeIdx][n*HH+f0] = x0;
        g_buf[storeIdx][n*HH+f1] = x1;
        unsigned lo = __ballot_sync(0xffffffffu, x0 >= THV);
        unsigned hi = __ballot_sync(0xffffffffu, x1 >= THV);
        if (lane == 0) g_bits[n] = (unsigned long long)lo | ((unsigned long long)hi << 32);
    }
}

__global__ void k_addstats(int yIdx, int st, const float* __restrict__ g,
                           const float* __restrict__ b, int addIdx, float scale,
                           int outIdx, int stOut) {
    int lane = threadIdx.x & 31;
    int wid = (blockIdx.x * blockDim.x + threadIdx.x) >> 5;
    int nw = (gridDim.x * blockDim.x) >> 5;
    int f0 = lane, f1 = lane + 32;
    float2 c0 = bn_coef(st, f0, g, b);
    float2 c1 = bn_coef(st, f1, g, b);
    const float* Y = g_buf[yIdx];
    const float* Ad = g_buf[addIdx];
    float* O = g_buf[outIdx];
    float ls0 = 0.f, lq0 = 0.f, ls1 = 0.f, lq1 = 0.f;
    for (int n = wid; n < NN; n += nw) {
        float t0 = fmaf(scale, fmaf(Y[n*HH+f0], c0.x, c0.y), Ad[n*HH+f0]);
        float t1 = fmaf(scale, fmaf(Y[n*HH+f1], c1.x, c1.y), Ad[n*HH+f1]);
        O[n*HH+f0] = t0; O[n*HH+f1] = t1;
        ls0 += t0; lq0 = fmaf(t0, t0, lq0);
        ls1 += t1; lq1 = fmaf(t1, t1, lq1);
    }
    __shared__ float ss[64], sq[64];
    if (threadIdx.x < 64) { ss[threadIdx.x] = 0.f; sq[threadIdx.x] = 0.f; }
    __syncthreads();
    atomicAdd(&ss[f0], ls0); atomicAdd(&sq[f0], lq0);
    atomicAdd(&ss[f1], ls1); atomicAdd(&sq[f1], lq1);
    __syncthreads();
    if (threadIdx.x < 64) {
        atomicAdd(&g_stats[stOut][0][threadIdx.x], (double)ss[threadIdx.x]);
        atomicAdd(&g_stats[stOut][1][threadIdx.x], (double)sq[threadIdx.x]);
    }
}

__global__ void k_qkv(int qIdx, int kIdx, int vIdx, int stq, int stk, int stv,
                      const float* __restrict__ bng, const float* __restrict__ bnb) {
    int lane = threadIdx.x & 31;
    int wid = (blockIdx.x * blockDim.x + threadIdx.x) >> 5;
    int nw = (gridDim.x * blockDim.x) >> 5;
    int f0 = lane, f1 = lane + 32;
    float2 q0 = bn_coef(stq, f0, bng + 4*HH, bnb + 4*HH);
    float2 q1 = bn_coef(stq, f1, bng + 4*HH, bnb + 4*HH);
    float2 k0 = bn_coef(stk, f0, bng + 5*HH, bnb + 5*HH);
    float2 k1 = bn_coef(stk, f1, bng + 5*HH, bnb + 5*HH);
    float2 v0 = bn_coef(stv, f0, bng + 6*HH, bnb + 6*HH);
    float2 v1 = bn_coef(stv, f1, bng + 6*HH, bnb + 6*HH);
    const float* Yq = g_buf[qIdx];
    const float* Yk = g_buf[kIdx];
    const float* Yv = g_buf[vIdx];
    for (int n = wid; n < NN; n += nw) {
        unsigned qlo = __ballot_sync(0xffffffffu, fmaf(Yq[n*HH+f0], q0.x, q0.y) >= THV);
        unsigned qhi = __ballot_sync(0xffffffffu, fmaf(Yq[n*HH+f1], q1.x, q1.y) >= THV);
        unsigned klo = __ballot_sync(0xffffffffu, fmaf(Yk[n*HH+f0], k0.x, k0.y) >= THV);
        unsigned khi = __ballot_sync(0xffffffffu, fmaf(Yk[n*HH+f1], k1.x, k1.y) >= THV);
        unsigned vlo = __ballot_sync(0xffffffffu, fmaf(Yv[n*HH+f0], v0.x, v0.y) >= THV);
        unsigned vhi = __ballot_sync(0xffffffffu, fmaf(Yv[n*HH+f1], v1.x, v1.y) >= THV);
        int pc = __popc(qlo & klo) + __popc(qhi & khi);
        bool att = ((float)pc * (1.0f / 64.0f)) >= ATTV;
        if (lane == 0)
            g_bits[n] = att ? ((unsigned long long)vlo | ((unsigned long long)vhi << 32)) : 0ull;
    }
}

__global__ void k_dec(int tIdx, int st, const float* __restrict__ g,
                      const float* __restrict__ b, float* __restrict__ out) {
    int lane = threadIdx.x & 31;
    int wid = (blockIdx.x * blockDim.x + threadIdx.x) >> 5;
    int nw = (gridDim.x * blockDim.x) >> 5;
    int f0 = lane, f1 = lane + 32;
    float2 c0 = bn_coef(st, f0, g, b);
    float2 c1 = bn_coef(st, f1, g, b);
    const float* T = g_buf[tIdx];
    float w0 = g_wsum[f0], w1 = g_wsum[f1];
    for (int n = wid; n < NN; n += nw) {
        float s = (fmaf(T[n*HH+f0], c0.x, c0.y)) * w0 + (fmaf(T[n*HH+f1], c1.x, c1.y)) * w1;
        #pragma unroll
        for (int o = 16; o > 0; o >>= 1) s += __shfl_down_sync(0xffffffffu, s, o);
        if (lane == 0) out[n] = s;
    }
}

// ---------------- host orchestration ----------------
static void run_enc(int p, const float* Wg, const float* bg,
                    const float* bng, const float* bnb, float* out) {
    int base = 9 * p;
    const int T = 256;
    k_gemm<<<391, 128>>>(p, Wg + 0*HH*HH, bg + 0*HH, 2, base + 0);
    k_lif<<<EB, T>>>(2, base + 0, bng + 0*HH, bnb + 0*HH, -1);
    k_aggbits<<<EB, T>>>(p, 5);
    k_gemm<<<391, 128>>>(5, Wg + 1*HH*HH, bg + 1*HH, 2, base + 1);
    k_bnspike<<<EB, T>>>(2, base + 1, bng + 1*HH, bnb + 1*HH, 3);
    k_aggbits<<<EB, T>>>(p, 5);
    k_gemm<<<391, 128>>>(5, Wg + 2*HH*HH, bg + 2*HH, 2, base + 2);
    k_addstats<<<EB, T>>>(2, base + 2, bng + 2*HH, bnb + 2*HH, 3, 1.0f, 4, base + 3);
    k_lif<<<EB, T>>>(4, base + 3, bng + 3*HH, bnb + 3*HH, 4);
    k_aggbits<<<EB, T>>>(p, 5);
    k_gemmQKV<<<dim3(391, 3), 128>>>(Wg, bg, base + 4);
    k_qkv<<<EB, T>>>(2, 3, 0, base + 4, base + 5, base + 6, bng, bnb);
    k_aggbits<<<EB, T>>>(p, 5);
    k_gemm<<<391, 128>>>(5, Wg + 6*HH*HH, bg + 6*HH, 2, base + 7);
    k_addstats<<<EB, T>>>(2, base + 7, bng + 7*HH, bnb + 7*HH, 4, 0.125f, 3, base + 8);
    k_dec<<<EB, T>>>(3, base + 8, bng + 8*HH, bnb + 8*HH, out);
}

extern "C" void kernel_launch(void* const* d_in, const int* in_sizes, int n_in,
                              void* d_out, int out_size) {
    const float* x   = (const float*)d_in[0];
    const int*   ei  = (const int*)d_in[1];
    const int*   mk  = (const int*)d_in[2];
    const float* Wg  = (const float*)d_in[3];
    const float* bg  = (const float*)d_in[4];
    const float* bng = (const float*)d_in[5];
    const float* bnb = (const float*)d_in[6];
    const float* Wl  = (const float*)d_in[7];
    float* out = (float*)d_out;

    k_zero<<<EB, 256>>>(Wl);            // 1
    k_count<<<EB, 256>>>(ei, mk);       // 2
    k_scanA<<<SBLK, 1024>>>();          // 3
    k_scanC<<<391, 256>>>();            // 4 (scanB folded in)
    k_scatter<<<EB, 256>>>(ei, mk);     // 5
    k_agg_dual<<<EB, 256>>>(x);         // 6  <- ncu (-s 5 -c 1) profiles this

    run_enc(0, Wg, bg, bng, bnb, out);
    run_enc(1, Wg, bg, bng, bnb, out + NN);
}

// round 6
// speedup vs baseline: 1.6603x; 1.0727x over previous
#include <cuda_runtime.h>

#define NN 100000
#define EE 1600000
#define HH 64
#define THV 0.7f
#define ATTV 0.2f
#define EPSV 1e-5f
#define SBLK 98
#define EB 1184          // one-wave grid

__device__ float g_buf[6][NN*HH];
__device__ float g_V[NN*HH];
__device__ unsigned long long g_bits[NN];
__device__ int g_cnt1[NN], g_cnt2[NN];
__device__ int g_rowptr1[NN+1], g_cursor1[NN];
__device__ int g_rowptr2[NN+1], g_cursor2[NN];
__device__ long long g_e1[EE];            // {coef_bits:hi, src:lo}
__device__ long long g_e2[EE];            // masked edges only
__device__ float g_dis1[NN], g_dis2[NN];
__device__ double g_stats[18][2][HH];
__device__ float g_wsum[HH];
__device__ int g_agg1[SBLK], g_agg2[SBLK], g_flag[SBLK];

// ---------------- f32x2 helpers ----------------
__device__ __forceinline__ unsigned long long pk2(float x, float y) {
    unsigned long long r; asm("mov.b64 %0,{%1,%2};" : "=l"(r) : "f"(x), "f"(y)); return r;
}
__device__ __forceinline__ float2 up2(unsigned long long v) {
    float2 r; asm("mov.b64 {%0,%1},%2;" : "=f"(r.x), "=f"(r.y) : "l"(v)); return r;
}
__device__ __forceinline__ void fma2(unsigned long long& d, unsigned long long a, unsigned long long b) {
    asm("fma.rn.f32x2 %0,%1,%2,%0;" : "+l"(d) : "l"(a), "l"(b));
}

// ---------------- setup ----------------
// cnt/stats/V/flags are zero on entry: static zero-init on call 1, k_cleanup thereafter.
__global__ void k_count(const int* __restrict__ ei, const int* __restrict__ mk,
                        const float* __restrict__ Wl) {
    int stride = gridDim.x * blockDim.x;
    for (int e = blockIdx.x * blockDim.x + threadIdx.x; e < EE; e += stride) {
        int dst = ei[EE + e];
        atomicAdd(&g_cnt1[dst], 1);
        if (mk[e]) atomicAdd(&g_cnt2[dst], 1);
    }
    if (blockIdx.x == 0 && threadIdx.x < HH) {
        float s = 0.f;
        for (int j = 0; j < HH; j++) s += Wl[threadIdx.x*HH + j];
        g_wsum[threadIdx.x] = s;
    }
}

__device__ __forceinline__ int blk_scan(int v, int t, int* sw) {
    int x = v;
    #pragma unroll
    for (int o = 1; o < 32; o <<= 1) {
        int y = __shfl_up_sync(0xffffffffu, x, o);
        if ((t & 31) >= o) x += y;
    }
    if ((t & 31) == 31) sw[t >> 5] = x;
    __syncthreads();
    if (t < 32) {
        int y = sw[t], z = y;
        #pragma unroll
        for (int o = 1; o < 32; o <<= 1) {
            int w = __shfl_up_sync(0xffffffffu, z, o);
            if (t >= o) z += w;
        }
        sw[t] = z - y;
    }
    __syncthreads();
    return x + sw[t >> 5];
}

// single-pass dual scan, decoupled lookback (98 blocks, all resident)
__global__ void k_scan() {
    __shared__ int sw1[32], sw2[32];
    __shared__ int soff1, soff2;
    int t = threadIdx.x, b = blockIdx.x;
    int i = b * 1024 + t;
    int c1 = (i < NN) ? g_cnt1[i] : 0;
    int c2 = (i < NN) ? g_cnt2[i] : 0;
    int incl1 = blk_scan(c1, t, sw1);
    __syncthreads();
    int incl2 = blk_scan(c2, t, sw2);
    if (t == 1023) {
        atomicExch(&g_agg1[b], incl1);
        atomicExch(&g_agg2[b], incl2);
        __threadfence();
        atomicExch(&g_flag[b], 1);
    }
    if (t < 32) {
        int o1 = 0, o2 = 0;
        for (int j = t; j < b; j += 32) {
            while (atomicAdd(&g_flag[j], 0) == 0) { }
            o1 += atomicAdd(&g_agg1[j], 0);
            o2 += atomicAdd(&g_agg2[j], 0);
        }
        #pragma unroll
        for (int o = 16; o > 0; o >>= 1) {
            o1 += __shfl_down_sync(0xffffffffu, o1, o);
            o2 += __shfl_down_sync(0xffffffffu, o2, o);
        }
        if (t == 0) { soff1 = o1; soff2 = o2; }
    }
    __syncthreads();
    if (i < NN) {
        int r1 = soff1 + incl1 - c1;
        int r2 = soff2 + incl2 - c2;
        g_rowptr1[i] = r1; g_cursor1[i] = r1;
        g_rowptr2[i] = r2; g_cursor2[i] = r2;
        g_dis1[i] = rsqrtf(1.0f + (float)c1);
        g_dis2[i] = rsqrtf(1.0f + (float)c2);
    }
    if (b == SBLK - 1 && t == 1023) {
        g_rowptr1[NN] = soff1 + incl1;
        g_rowptr2[NN] = soff2 + incl2;
    }
}

__global__ void k_scatter(const int* __restrict__ ei, const int* __restrict__ mk) {
    int stride = gridDim.x * blockDim.x;
    for (int e = blockIdx.x * blockDim.x + threadIdx.x; e < EE; e += stride) {
        int src = ei[e], dst = ei[EE + e];
        float c1 = g_dis1[src] * g_dis1[dst];
        int p1 = atomicAdd(&g_cursor1[dst], 1);
        g_e1[p1] = ((long long)__float_as_int(c1) << 32) | (unsigned)src;
        if (mk[e]) {
            float c2 = g_dis2[src] * g_dis2[dst];
            int p2 = atomicAdd(&g_cursor2[dst], 1);
            g_e2[p2] = ((long long)__float_as_int(c2) << 32) | (unsigned)src;
        }
    }
}

// restore invariants for next graph replay (runs last)
__global__ void k_cleanup() {
    int stride = gridDim.x * blockDim.x;
    for (int i = blockIdx.x * blockDim.x + threadIdx.x; i < NN*HH; i += stride) {
        g_V[i] = 0.f;
        if (i < NN) { g_cnt1[i] = 0; g_cnt2[i] = 0; }
        if (i < 18*2*HH) ((double*)g_stats)[i] = 0.0;
        if (i < SBLK) g_flag[i] = 0;
    }
}

// ---------------- aggregations ----------------
__global__ void k_agg_dual(const float* __restrict__ x) {
    int lane = threadIdx.x & 31;
    int w0id = (blockIdx.x * blockDim.x + threadIdx.x) >> 5;
    int nw = (gridDim.x * blockDim.x) >> 5;
    int f0 = lane, f1 = lane + 32;
    for (int n = w0id; n < NN; n += nw) {
        float d1 = g_dis1[n], d2 = g_dis2[n];
        float x0 = x[n*HH + f0], x1 = x[n*HH + f1];
        float a10 = d1*d1*x0, a11 = d1*d1*x1;
        float a20 = d2*d2*x0, a21 = d2*d2*x1;
        int s = g_rowptr1[n], e = g_rowptr1[n+1];
        int i = s;
        for (; i + 4 <= e; i += 4) {
            long long q0 = g_e1[i],   q1 = g_e1[i+1];
            long long q2 = g_e1[i+2], q3 = g_e1[i+3];
            int s0 = (int)q0, s1 = (int)q1, s2 = (int)q2, s3 = (int)q3;
            float y00 = x[s0*HH+f0], y01 = x[s0*HH+f1];
            float y10 = x[s1*HH+f0], y11 = x[s1*HH+f1];
            float y20 = x[s2*HH+f0], y21 = x[s2*HH+f1];
            float y30 = x[s3*HH+f0], y31 = x[s3*HH+f1];
            float c0 = __int_as_float((int)(q0 >> 32));
            float c1 = __int_as_float((int)(q1 >> 32));
            float c2 = __int_as_float((int)(q2 >> 32));
            float c3 = __int_as_float((int)(q3 >> 32));
            a10 = fmaf(c0, y00, a10); a11 = fmaf(c0, y01, a11);
            a10 = fmaf(c1, y10, a10); a11 = fmaf(c1, y11, a11);
            a10 = fmaf(c2, y20, a10); a11 = fmaf(c2, y21, a11);
            a10 = fmaf(c3, y30, a10); a11 = fmaf(c3, y31, a11);
        }
        for (; i < e; i++) {
            long long q = g_e1[i];
            float y0 = x[(int)q*HH+f0], y1 = x[(int)q*HH+f1];
            float c = __int_as_float((int)(q >> 32));
            a10 = fmaf(c, y0, a10); a11 = fmaf(c, y1, a11);
        }
        s = g_rowptr2[n]; e = g_rowptr2[n+1];
        for (i = s; i < e; i++) {
            long long q = g_e2[i];
            float y0 = x[(int)q*HH+f0], y1 = x[(int)q*HH+f1];
            float c = __int_as_float((int)(q >> 32));
            a20 = fmaf(c, y0, a20); a21 = fmaf(c, y1, a21);
        }
        g_buf[0][n*HH+f0] = a10; g_buf[0][n*HH+f1] = a11;
        g_buf[1][n*HH+f0] = a20; g_buf[1][n*HH+f1] = a21;
    }
}

__global__ void k_aggbits(int pass, int outIdx) {
    int lane = threadIdx.x & 31;
    int w0id = (blockIdx.x * blockDim.x + threadIdx.x) >> 5;
    int nw = (gridDim.x * blockDim.x) >> 5;
    const int* rp = pass ? g_rowptr2 : g_rowptr1;
    const long long* ep = pass ? g_e2 : g_e1;
    int sh = 31 - lane;
    for (int n = w0id; n < NN; n += nw) {
        float d = pass ? g_dis2[n] : g_dis1[n];
        unsigned long long sb = g_bits[n];
        float self = d*d;
        float a0 = (((unsigned)sb         >> lane) & 1u) ? self : 0.f;
        float a1 = (((unsigned)(sb >> 32) >> lane) & 1u) ? self : 0.f;
        int s = rp[n], e = rp[n+1];
        int i = s;
        for (; i + 4 <= e; i += 4) {
            long long q0 = ep[i],   q1 = ep[i+1];
            long long q2 = ep[i+2], q3 = ep[i+3];
            unsigned long long b0 = g_bits[(int)q0], b1 = g_bits[(int)q1];
            unsigned long long b2 = g_bits[(int)q2], b3 = g_bits[(int)q3];
            int c0 = (int)(q0 >> 32), c1 = (int)(q1 >> 32);
            int c2 = (int)(q2 >> 32), c3 = (int)(q3 >> 32);
            int m;
            m = ((int)((unsigned)b0         << sh)) >> 31; a0 += __int_as_float(c0 & m);
            m = ((int)((unsigned)(b0 >> 32) << sh)) >> 31; a1 += __int_as_float(c0 & m);
            m = ((int)((unsigned)b1         << sh)) >> 31; a0 += __int_as_float(c1 & m);
            m = ((int)((unsigned)(b1 >> 32) << sh)) >> 31; a1 += __int_as_float(c1 & m);
            m = ((int)((unsigned)b2         << sh)) >> 31; a0 += __int_as_float(c2 & m);
            m = ((int)((unsigned)(b2 >> 32) << sh)) >> 31; a1 += __int_as_float(c2 & m);
            m = ((int)((unsigned)b3         << sh)) >> 31; a0 += __int_as_float(c3 & m);
            m = ((int)((unsigned)(b3 >> 32) << sh)) >> 31; a1 += __int_as_float(c3 & m);
        }
        for (; i < e; i++) {
            long long q = ep[i];
            unsigned long long b = g_bits[(int)q];
            int c = (int)(q >> 32);
            int m;
            m = ((int)((unsigned)b         << sh)) >> 31; a0 += __int_as_float(c & m);
            m = ((int)((unsigned)(b >> 32) << sh)) >> 31; a1 += __int_as_float(c & m);
        }
        g_buf[outIdx][n*HH+lane]    = a0;
        g_buf[outIdx][n*HH+lane+32] = a1;
    }
}

// ---------------- GEMM core (f32x2), 2 tiles per block ----------------
__device__ __forceinline__ void gemm_body(const float* __restrict__ A,
                                          const float* __restrict__ W,
                                          const float* __restrict__ bias,
                                          float* __restrict__ Y, int st,
                                          int tid, float* As, float* Ws) {
    const float4* W4 = (const float4*)W;
    float4* Ws4 = (float4*)Ws;
    #pragma unroll
    for (int i = 0; i < 8; i++) Ws4[tid + 128*i] = W4[tid + 128*i];

    int cx = tid & 7, ry = tid >> 3;
    float b8[8];
    #pragma unroll
    for (int c = 0; c < 8; c++) b8[c] = bias[8*cx + c];
    float ls[8], lq[8];
    #pragma unroll
    for (int c = 0; c < 8; c++) { ls[c] = 0.f; lq[c] = 0.f; }

    #pragma unroll 1
    for (int t = 0; t < 2; t++) {
        int base = (blockIdx.x * 2 + t) * 128;
        __syncthreads();
        int row = base + tid;
        if (row < NN) {
            const float4* Ar = (const float4*)(A + row*HH);
            #pragma unroll
            for (int v = 0; v < 16; v++) {
                float4 q = Ar[v];
                As[(4*v+0)*128 + tid] = q.x; As[(4*v+1)*128 + tid] = q.y;
                As[(4*v+2)*128 + tid] = q.z; As[(4*v+3)*128 + tid] = q.w;
            }
        } else {
            #pragma unroll
            for (int v = 0; v < 64; v++) As[v*128 + tid] = 0.f;
        }
        __syncthreads();

        unsigned long long acc[4][8];
        #pragma unroll
        for (int p = 0; p < 4; p++)
            #pragma unroll
            for (int c = 0; c < 8; c++) acc[p][c] = 0ull;

        #pragma unroll 2
        for (int k = 0; k < 64; k++) {
            const float* ap = &As[k*128 + 8*ry];
            unsigned long long a0 = *(const unsigned long long*)(ap);
            unsigned long long a1 = *(const unsigned long long*)(ap + 2);
            unsigned long long a2 = *(const unsigned long long*)(ap + 4);
            unsigned long long a3 = *(const unsigned long long*)(ap + 6);
            float4 w0 = *(const float4*)&Ws[k*64 + 8*cx];
            float4 w1 = *(const float4*)&Ws[k*64 + 8*cx + 4];
            unsigned long long wd[8];
            wd[0] = pk2(w0.x, w0.x); wd[1] = pk2(w0.y, w0.y);
            wd[2] = pk2(w0.z, w0.z); wd[3] = pk2(w0.w, w0.w);
            wd[4] = pk2(w1.x, w1.x); wd[5] = pk2(w1.y, w1.y);
            wd[6] = pk2(w1.z, w1.z); wd[7] = pk2(w1.w, w1.w);
            #pragma unroll
            for (int c = 0; c < 8; c++) {
                fma2(acc[0][c], a0, wd[c]);
                fma2(acc[1][c], a1, wd[c]);
                fma2(acc[2][c], a2, wd[c]);
                fma2(acc[3][c], a3, wd[c]);
            }
        }

        #pragma unroll
        for (int p = 0; p < 4; p++) {
            float vlo[8], vhi[8];
            #pragma unroll
            for (int c = 0; c < 8; c++) {
                float2 tt = up2(acc[p][c]);
                vlo[c] = tt.x + b8[c];
                vhi[c] = tt.y + b8[c];
            }
            int r0 = base + 8*ry + 2*p, r1 = r0 + 1;
            if (r0 < NN) {
                #pragma unroll
                for (int c = 0; c < 8; c++) { ls[c] += vlo[c]; lq[c] = fmaf(vlo[c], vlo[c], lq[c]); }
                *(float4*)&Y[r0*HH + 8*cx]     = make_float4(vlo[0],vlo[1],vlo[2],vlo[3]);
                *(float4*)&Y[r0*HH + 8*cx + 4] = make_float4(vlo[4],vlo[5],vlo[6],vlo[7]);
            }
            if (r1 < NN) {
                #pragma unroll
                for (int c = 0; c < 8; c++) { ls[c] += vhi[c]; lq[c] = fmaf(vhi[c], vhi[c], lq[c]); }
                *(float4*)&Y[r1*HH + 8*cx]     = make_float4(vhi[0],vhi[1],vhi[2],vhi[3]);
                *(float4*)&Y[r1*HH + 8*cx + 4] = make_float4(vhi[4],vhi[5],vhi[6],vhi[7]);
            }
        }
    }

    __syncthreads();
    float* ssum = As;
    float* ssq  = As + 64;
    if (tid < 64) { ssum[tid] = 0.f; ssq[tid] = 0.f; }
    __syncthreads();
    #pragma unroll
    for (int c = 0; c < 8; c++) {
        atomicAdd(&ssum[8*cx + c], ls[c]);
        atomicAdd(&ssq[8*cx + c],  lq[c]);
    }
    __syncthreads();
    if (tid < 64) {
        atomicAdd(&g_stats[st][0][tid], (double)ssum[tid]);
        atomicAdd(&g_stats[st][1][tid], (double)ssq[tid]);
    }
}

__global__ void __launch_bounds__(128) k_gemm(int aIdx, const float* __restrict__ W,
                                              const float* __restrict__ bias,
                                              int yIdx, int st) {
    __shared__ float As[64*128];
    __shared__ float Ws[64*64];
    gemm_body(g_buf[aIdx], W, bias, g_buf[yIdx], st, threadIdx.x, As, Ws);
}

__global__ void __launch_bounds__(128) k_gemmQKV(const float* __restrict__ Wg,
                                                 const float* __restrict__ bg, int stBase) {
    __shared__ float As[64*128];
    __shared__ float Ws[64*64];
    int y = blockIdx.y;
    int outIdx = (y == 0) ? 2 : (y == 1) ? 3 : 0;
    gemm_body(g_buf[5], Wg + (3+y)*HH*HH, bg + (3+y)*HH, g_buf[outIdx],
              stBase + y, threadIdx.x, As, Ws);
}

// ---------------- BN helper ----------------
__device__ __forceinline__ float2 bn_coef(int st, int f, const float* __restrict__ g,
                                          const float* __restrict__ b) {
    double s = g_stats[st][0][f], q = g_stats[st][1][f];
    double mean = s * (1.0 / NN);
    float var = (float)(q * (1.0 / NN) - mean * mean);
    float rstd = rsqrtf(var + EPSV);
    float sc = g[f] * rstd;
    float sh = b[f] - (float)mean * sc;
    return make_float2(sc, sh);
}

__global__ void k_lif(int yIdx, int st, const float* __restrict__ g,
                      const float* __restrict__ b, int storeIdx) {
    int lane = threadIdx.x & 31;
    int wid = (blockIdx.x * blockDim.x + threadIdx.x) >> 5;
    int nw = (gridDim.x * blockDim.x) >> 5;
    int f0 = lane, f1 = lane + 32;
    float2 c0 = bn_coef(st, f0, g, b);
    float2 c1 = bn_coef(st, f1, g, b);
    const float* Y = g_buf[yIdx];
    for (int n = wid; n < NN; n += nw) {
        float x0 = fmaf(Y[n*HH+f0], c0.x, c0.y);
        float x1 = fmaf(Y[n*HH+f1], c1.x, c1.y);
        if (storeIdx >= 0) { g_buf[storeIdx][n*HH+f0] = x0; g_buf[storeIdx][n*HH+f1] = x1; }
        float v0 = g_V[n*HH+f0] + x0;
        float v1 = g_V[n*HH+f1] + x1;
        bool s0 = v0 >= THV, s1 = v1 >= THV;
        g_V[n*HH+f0] = s0 ? 0.f : v0;
        g_V[n*HH+f1] = s1 ? 0.f : v1;
        unsigned lo = __ballot_sync(0xffffffffu, s0);
        unsigned hi = __ballot_sync(0xffffffffu, s1);
        if (lane == 0) g_bits[n] = (unsigned long long)lo | ((unsigned long long)hi << 32);
    }
}

__global__ void k_bnspike(int yIdx, int st, const float* __restrict__ g,
                          const float* __restrict__ b, int storeIdx) {
    int lane = threadIdx.x & 31;
    int wid = (blockIdx.x * blockDim.x + threadIdx.x) >> 5;
    int nw = (gridDim.x * blockDim.x) >> 5;
    int f0 = lane, f1 = lane + 32;
    float2 c0 = bn_coef(st, f0, g, b);
    float2 c1 = bn_coef(st, f1, g, b);
    const float* Y = g_buf[yIdx];
    for (int n = wid; n < NN; n += nw) {
        float x0 = fmaf(Y[n*HH+f0], c0.x, c0.y);
        float x1 = fmaf(Y[n*HH+f1], c1.x, c1.y);
        g_buf[storeIdx][n*HH+f0] = x0;
        g_buf[storeIdx][n*HH+f1] = x1;
        unsigned lo = __ballot_sync(0xffffffffu, x0 >= THV);
        unsigned hi = __ballot_sync(0xffffffffu, x1 >= THV);
        if (lane == 0) g_bits[n] = (unsigned long long)lo | ((unsigned long long)hi << 32);
    }
}

__global__ void k_addstats(int yIdx, int st, const float* __restrict__ g,
                           const float* __restrict__ b, int addIdx, float scale,
                           int outIdx, int stOut) {
    int lane = threadIdx.x & 31;
    int wid = (blockIdx.x * blockDim.x + threadIdx.x) >> 5;
    int nw = (gridDim.x * blockDim.x) >> 5;
    int f0 = lane, f1 = lane + 32;
    float2 c0 = bn_coef(st, f0, g, b);
    float2 c1 = bn_coef(st, f1, g, b);
    const float* Y = g_buf[yIdx];
    const float* Ad = g_buf[addIdx];
    float* O = g_buf[outIdx];
    float ls0 = 0.f, lq0 = 0.f, ls1 = 0.f, lq1 = 0.f;
    for (int n = wid; n < NN; n += nw) {
        float t0 = fmaf(scale, fmaf(Y[n*HH+f0], c0.x, c0.y), Ad[n*HH+f0]);
        float t1 = fmaf(scale, fmaf(Y[n*HH+f1], c1.x, c1.y), Ad[n*HH+f1]);
        O[n*HH+f0] = t0; O[n*HH+f1] = t1;
        ls0 += t0; lq0 = fmaf(t0, t0, lq0);
        ls1 += t1; lq1 = fmaf(t1, t1, lq1);
    }
    __shared__ float ss[64], sq[64];
    if (threadIdx.x < 64) { ss[threadIdx.x] = 0.f; sq[threadIdx.x] = 0.f; }
    __syncthreads();
    atomicAdd(&ss[f0], ls0); atomicAdd(&sq[f0], lq0);
    atomicAdd(&ss[f1], ls1); atomicAdd(&sq[f1], lq1);
    __syncthreads();
    if (threadIdx.x < 64) {
        atomicAdd(&g_stats[stOut][0][threadIdx.x], (double)ss[threadIdx.x]);
        atomicAdd(&g_stats[stOut][1][threadIdx.x], (double)sq[threadIdx.x]);
    }
}

__global__ void k_qkv(int qIdx, int kIdx, int vIdx, int stq, int stk, int stv,
                      const float* __restrict__ bng, const float* __restrict__ bnb) {
    int lane = threadIdx.x & 31;
    int wid = (blockIdx.x * blockDim.x + threadIdx.x) >> 5;
    int nw = (gridDim.x * blockDim.x) >> 5;
    int f0 = lane, f1 = lane + 32;
    float2 q0 = bn_coef(stq, f0, bng + 4*HH, bnb + 4*HH);
    float2 q1 = bn_coef(stq, f1, bng + 4*HH, bnb + 4*HH);
    float2 k0 = bn_coef(stk, f0, bng + 5*HH, bnb + 5*HH);
    float2 k1 = bn_coef(stk, f1, bng + 5*HH, bnb + 5*HH);
    float2 v0 = bn_coef(stv, f0, bng + 6*HH, bnb + 6*HH);
    float2 v1 = bn_coef(stv, f1, bng + 6*HH, bnb + 6*HH);
    const float* Yq = g_buf[qIdx];
    const float* Yk = g_buf[kIdx];
    const float* Yv = g_buf[vIdx];
    for (int n = wid; n < NN; n += nw) {
        unsigned qlo = __ballot_sync(0xffffffffu, fmaf(Yq[n*HH+f0], q0.x, q0.y) >= THV);
        unsigned qhi = __ballot_sync(0xffffffffu, fmaf(Yq[n*HH+f1], q1.x, q1.y) >= THV);
        unsigned klo = __ballot_sync(0xffffffffu, fmaf(Yk[n*HH+f0], k0.x, k0.y) >= THV);
        unsigned khi = __ballot_sync(0xffffffffu, fmaf(Yk[n*HH+f1], k1.x, k1.y) >= THV);
        unsigned vlo = __ballot_sync(0xffffffffu, fmaf(Yv[n*HH+f0], v0.x, v0.y) >= THV);
        unsigned vhi = __ballot_sync(0xffffffffu, fmaf(Yv[n*HH+f1], v1.x, v1.y) >= THV);
        int pc = __popc(qlo & klo) + __popc(qhi & khi);
        bool att = ((float)pc * (1.0f / 64.0f)) >= ATTV;
        if (lane == 0)
            g_bits[n] = att ? ((unsigned long long)vlo | ((unsigned long long)vhi << 32)) : 0ull;
    }
}

__global__ void k_dec(int tIdx, int st, const float* __restrict__ g,
                      const float* __restrict__ b, float* __restrict__ out) {
    int lane = threadIdx.x & 31;
    int wid = (blockIdx.x * blockDim.x + threadIdx.x) >> 5;
    int nw = (gridDim.x * blockDim.x) >> 5;
    int f0 = lane, f1 = lane + 32;
    float2 c0 = bn_coef(st, f0, g, b);
    float2 c1 = bn_coef(st, f1, g, b);
    const float* T = g_buf[tIdx];
    float w0 = g_wsum[f0], w1 = g_wsum[f1];
    for (int n = wid; n < NN; n += nw) {
        float s = (fmaf(T[n*HH+f0], c0.x, c0.y)) * w0 + (fmaf(T[n*HH+f1], c1.x, c1.y)) * w1;
        #pragma unroll
        for (int o = 16; o > 0; o >>= 1) s += __shfl_down_sync(0xffffffffu, s, o);
        if (lane == 0) out[n] = s;
    }
}

// ---------------- host orchestration ----------------
static void run_enc(int p, const float* Wg, const float* bg,
                    const float* bng, const float* bnb, float* out) {
    int base = 9 * p;
    const int T = 256;
    k_gemm<<<391, 128>>>(p, Wg + 0*HH*HH, bg + 0*HH, 2, base + 0);
    k_lif<<<EB, T>>>(2, base + 0, bng + 0*HH, bnb + 0*HH, -1);
    k_aggbits<<<EB, T>>>(p, 5);
    k_gemm<<<391, 128>>>(5, Wg + 1*HH*HH, bg + 1*HH, 2, base + 1);
    k_bnspike<<<EB, T>>>(2, base + 1, bng + 1*HH, bnb + 1*HH, 3);
    k_aggbits<<<EB, T>>>(p, 5);
    k_gemm<<<391, 128>>>(5, Wg + 2*HH*HH, bg + 2*HH, 2, base + 2);
    k_addstats<<<EB, T>>>(2, base + 2, bng + 2*HH, bnb + 2*HH, 3, 1.0f, 4, base + 3);
    k_lif<<<EB, T>>>(4, base + 3, bng + 3*HH, bnb + 3*HH, 4);
    k_aggbits<<<EB, T>>>(p, 5);
    k_gemmQKV<<<dim3(391, 3), 128>>>(Wg, bg, base + 4);
    k_qkv<<<EB, T>>>(2, 3, 0, base + 4, base + 5, base + 6, bng, bnb);
    k_aggbits<<<EB, T>>>(p, 5);
    k_gemm<<<391, 128>>>(5, Wg + 6*HH*HH, bg + 6*HH, 2, base + 7);
    k_addstats<<<EB, T>>>(2, base + 7, bng + 7*HH, bnb + 7*HH, 4, 0.125f, 3, base + 8);
    k_dec<<<EB, T>>>(3, base + 8, bng + 8*HH, bnb + 8*HH, out);
}

extern "C" void kernel_launch(void* const* d_in, const int* in_sizes, int n_in,
                              void* d_out, int out_size) {
    const float* x   = (const float*)d_in[0];
    const int*   ei  = (const int*)d_in[1];
    const int*   mk  = (const int*)d_in[2];
    const float* Wg  = (const float*)d_in[3];
    const float* bg  = (const float*)d_in[4];
    const float* bng = (const float*)d_in[5];
    const float* bnb = (const float*)d_in[6];
    const float* Wl  = (const float*)d_in[7];
    float* out = (float*)d_out;

    k_count<<<EB, 256>>>(ei, mk, Wl);   // launch 0 (cnt/stats/V/flags zero by invariant)
    k_scan<<<SBLK, 1024>>>();           // launch 1 (fused scan, decoupled lookback)
    k_scatter<<<EB, 256>>>(ei, mk);     // launch 2
    k_agg_dual<<<EB, 256>>>(x);         // launch 3  <- ncu captures this

    run_enc(0, Wg, bg, bng, bnb, out);
    run_enc(1, Wg, bg, bng, bnb, out + NN);

    k_cleanup<<<EB, 256>>>();           // restore invariants for next replay
}